// round 1
// baseline (speedup 1.0000x reference)
#include <cuda_runtime.h>
#include <math.h>
#include <stdint.h>

// Problem constants
#define N_B   8192
#define N_K   10
#define N_D   128
#define N_T   128
#define N_QD  256
#define N_KD  384
#define M_HOP2 (N_B * N_K)          // 81920 rows (flattened first-hop neighbors)
#define P_HOP2 (M_HOP2 * N_K)       // 819200 (m,k) pairs for hop-2 attention

// ---------------- scratch (static __device__ globals; no allocs) ------------
__device__ float g_keyv[(size_t)P_HOP2 * N_KD];   // 1.26 GB, reused per layer
__device__ float g_Kp [(size_t)P_HOP2 * N_QD];    // key projections
__device__ float g_Vp [(size_t)P_HOP2 * N_QD];    // value projections
__device__ float g_E1 [(size_t)M_HOP2 * N_D];     // emb0(neighbors1) == hop2 src feats
__device__ float g_S  [(size_t)N_B   * N_D];      // emb0(src_nodes)
__device__ float g_Q  [(size_t)M_HOP2 * N_QD];
__device__ float g_AO [(size_t)M_HOP2 * N_QD];
__device__ float g_O1 [(size_t)M_HOP2 * N_QD];
__device__ float g_H  [(size_t)M_HOP2 * N_D];
__device__ float g_NL1[(size_t)M_HOP2 * N_D];     // neigh_l1
__device__ float g_SL1[(size_t)N_B   * N_D];      // src_l1
__device__ float g_cq [2 * N_QD];                 // per-param-set constant query part
__device__ int   g_inv[M_HOP2];

// ---------------- emb0 gather: out[r] = node_feat[idx[r]] + memory[idx[r]] --
__global__ void gather_emb_kernel(const float* __restrict__ nf,
                                  const float* __restrict__ mem,
                                  const int* __restrict__ idx,
                                  float* __restrict__ out, int n)
{
    int r = blockIdx.x;
    if (r >= n) return;
    int t = threadIdx.x;
    size_t s = (size_t)idx[r] * N_D + t;
    out[(size_t)r * N_D + t] = nf[s] + mem[s];
}

// ---------------- keyv builder: [emb || edge_feat || cos(dt*w+b)] -----------
__global__ void build_keyv_kernel(const int* __restrict__ neigh,
                                  const int* __restrict__ eidx,
                                  const float* __restrict__ etime,
                                  const float* __restrict__ ts, int ts_div,
                                  const float* __restrict__ nf,
                                  const float* __restrict__ mem,
                                  const float* __restrict__ ef,
                                  const float* __restrict__ dense_neigh, // null => gather emb0
                                  const float* __restrict__ tw,
                                  const float* __restrict__ tb,
                                  float* __restrict__ keyv, int Mrows)
{
    int r = blockIdx.x;
    if (r >= Mrows) return;
    int t = threadIdx.x;           // 128 threads
    float* out = keyv + (size_t)r * N_KD;
    if (dense_neigh) {
        out[t] = dense_neigh[(size_t)r * N_D + t];
    } else {
        size_t s = (size_t)neigh[r] * N_D + t;
        out[t] = nf[s] + mem[s];
    }
    out[N_D + t] = ef[(size_t)eidx[r] * N_D + t];
    int m = r / N_K;
    float d = ts[m / ts_div] - etime[r];
    // match jax op order exactly: mul then add, no fma contraction
    float arg = __fadd_rn(__fmul_rn(d, tw[t]), tb[t]);
    out[2 * N_D + t] = cosf(arg);
}

// ---------------- const query part: cq[j] = bq[j] + sum_t cos(tb[t])*Wq[j,128+t]
__global__ void const_q_kernel(const float* __restrict__ Wq,
                               const float* __restrict__ bq,
                               const float* __restrict__ tb,
                               float* __restrict__ cq)
{
    __shared__ float ct[N_T];
    int p = blockIdx.x;            // param set 0/1
    int j = threadIdx.x;           // 256
    if (j < N_T) ct[j] = cosf(tb[j]);
    __syncthreads();
    const float* W = Wq + (size_t)p * N_QD * N_QD;
    float s = bq[p * N_QD + j];
    #pragma unroll 4
    for (int t = 0; t < N_T; t++) s = fmaf(ct[t], W[(size_t)j * N_QD + N_D + t], s);
    cq[p * N_QD + j] = s;
}

// ---------------- generic tiled GEMM: C[M,N] (+)= A[M,Kd] @ W[N,*]^T ---------
#define GF_ACC  1
#define GF_RELU 2

__global__ __launch_bounds__(256) void gemm_kernel(
    const float* __restrict__ A, int lda,
    const float* __restrict__ W, int ldw, int wofs,
    float* __restrict__ C, int ldc,
    int M, int N, int Kd,
    const float* __restrict__ bias,
    int flags, const int* __restrict__ zmask)
{
    __shared__ float As[16][128];
    __shared__ float Ws[16][128];
    int tx = threadIdx.x & 15, ty = threadIdx.x >> 4;
    int m0 = blockIdx.y * 128, n0 = blockIdx.x * 128;

    float acc[8][8];
    #pragma unroll
    for (int i = 0; i < 8; i++)
        #pragma unroll
        for (int j = 0; j < 8; j++) acc[i][j] = 0.f;

    for (int k0 = 0; k0 < Kd; k0 += 16) {
        for (int s = threadIdx.x; s < 512; s += 256) {
            int row = s >> 2, kp = s & 3;
            float4 v = *(const float4*)&A[(size_t)(m0 + row) * lda + k0 + kp * 4];
            As[kp*4+0][row] = v.x; As[kp*4+1][row] = v.y;
            As[kp*4+2][row] = v.z; As[kp*4+3][row] = v.w;
        }
        for (int s = threadIdx.x; s < 512; s += 256) {
            int row = s >> 2, kp = s & 3;
            float4 v = *(const float4*)&W[(size_t)(n0 + row) * ldw + wofs + k0 + kp * 4];
            Ws[kp*4+0][row] = v.x; Ws[kp*4+1][row] = v.y;
            Ws[kp*4+2][row] = v.z; Ws[kp*4+3][row] = v.w;
        }
        __syncthreads();
        #pragma unroll
        for (int kk = 0; kk < 16; kk++) {
            float4 a0 = *(const float4*)&As[kk][ty*8];
            float4 a1 = *(const float4*)&As[kk][ty*8+4];
            float4 b0 = *(const float4*)&Ws[kk][tx*8];
            float4 b1 = *(const float4*)&Ws[kk][tx*8+4];
            float a[8] = {a0.x,a0.y,a0.z,a0.w,a1.x,a1.y,a1.z,a1.w};
            float b[8] = {b0.x,b0.y,b0.z,b0.w,b1.x,b1.y,b1.z,b1.w};
            #pragma unroll
            for (int i = 0; i < 8; i++)
                #pragma unroll
                for (int j = 0; j < 8; j++)
                    acc[i][j] = fmaf(a[i], b[j], acc[i][j]);
        }
        __syncthreads();
    }

    #pragma unroll
    for (int i = 0; i < 8; i++) {
        int m = m0 + ty * 8 + i;
        bool zero = (zmask != nullptr) && (zmask[m] != 0);
        #pragma unroll
        for (int j = 0; j < 8; j++) {
            int n = n0 + tx * 8 + j;
            float v = acc[i][j];
            if (flags & GF_ACC) v += C[(size_t)m * ldc + n];
            if (bias) v += bias[n];
            if (flags & GF_RELU) v = fmaxf(v, 0.f);
            if (zero) v = 0.f;
            C[(size_t)m * ldc + n] = v;
        }
    }
}

// ---------------- attention core: one warp per (row, head) ------------------
__global__ void attn_kernel(const float* __restrict__ Q,
                            const float* __restrict__ Kp,
                            const float* __restrict__ Vp,
                            const int* __restrict__ neigh,
                            float* __restrict__ AO,
                            int* __restrict__ inv, int M)
{
    int gw = (int)((blockIdx.x * (size_t)blockDim.x + threadIdx.x) >> 5);
    int lane = threadIdx.x & 31;
    if (gw >= M * 2) return;
    int m = gw >> 1, h = gw & 1;
    const float SC = 0.08838834764831843f;   // 1/sqrt(128)

    float4 q = *(const float4*)&Q[(size_t)m * N_QD + h * 128 + lane * 4];

    bool msk[N_K]; bool allm = true;
    #pragma unroll
    for (int k = 0; k < N_K; k++) {
        msk[k] = (neigh[m * N_K + k] == 0);
        allm = allm && msk[k];
    }

    float sc[N_K];
    #pragma unroll
    for (int k = 0; k < N_K; k++) {
        float4 kv = *(const float4*)&Kp[((size_t)m * N_K + k) * N_QD + h * 128 + lane * 4];
        float p = q.x*kv.x + q.y*kv.y + q.z*kv.z + q.w*kv.w;
        #pragma unroll
        for (int o = 16; o; o >>= 1) p += __shfl_xor_sync(0xffffffffu, p, o);
        float s = p * SC;
        bool mk = msk[k] && !(allm && k == 0);
        sc[k] = mk ? -1e9f : s;
    }
    float mx = sc[0];
    #pragma unroll
    for (int k = 1; k < N_K; k++) mx = fmaxf(mx, sc[k]);
    float sum = 0.f;
    #pragma unroll
    for (int k = 0; k < N_K; k++) { sc[k] = expf(sc[k] - mx); sum += sc[k]; }
    float rinv = 1.f / sum;

    float4 o = make_float4(0.f, 0.f, 0.f, 0.f);
    #pragma unroll
    for (int k = 0; k < N_K; k++) {
        float w = sc[k] * rinv;
        float4 v = *(const float4*)&Vp[((size_t)m * N_K + k) * N_QD + h * 128 + lane * 4];
        o.x = fmaf(w, v.x, o.x); o.y = fmaf(w, v.y, o.y);
        o.z = fmaf(w, v.z, o.z); o.w = fmaf(w, v.w, o.w);
    }
    *(float4*)&AO[(size_t)m * N_QD + h * 128 + lane * 4] = o;
    if (h == 0 && lane == 0) inv[m] = allm ? 1 : 0;
}

// ---------------- one temporal attention layer ------------------------------
static void run_layer(int M,
                      const float* src_feat,
                      const int* neigh, const float* dense_neigh,
                      const int* eidx, const float* etime,
                      const float* ts, int ts_div,
                      const float* nf, const float* mem, const float* ef,
                      const float* tw, const float* tb,
                      const float* Wq, const float* cq,
                      const float* Wk, const float* bk,
                      const float* Wv, const float* bv,
                      const float* Wo, const float* bo,
                      const float* W1, const float* b1,
                      const float* W2, const float* b2,
                      float* keyv, float* Kp, float* Vp, float* Qb,
                      float* AO, float* O1, float* H, int* inv,
                      float* out)
{
    int MK = M * N_K;
    build_keyv_kernel<<<MK, 128>>>(neigh, eidx, etime, ts, ts_div,
                                   nf, mem, ef, dense_neigh, tw, tb, keyv, MK);
    // q = src_feat @ Wq[:, :128]^T + cq   (cq = bq + time-part, precomputed)
    gemm_kernel<<<dim3(2, M/128), 256>>>(src_feat,128, Wq,256,0, Qb,256, M,256,128, cq, 0, nullptr);
    // k/v projections of keyv
    gemm_kernel<<<dim3(2, MK/128), 256>>>(keyv,384, Wk,384,0, Kp,256, MK,256,384, bk, 0, nullptr);
    gemm_kernel<<<dim3(2, MK/128), 256>>>(keyv,384, Wv,384,0, Vp,256, MK,256,384, bv, 0, nullptr);
    attn_kernel<<<(M*2*32 + 255)/256, 256>>>(Qb, Kp, Vp, neigh, AO, inv, M);
    // out @ Wo^T + bo, zeroed on invalid rows
    gemm_kernel<<<dim3(2, M/128), 256>>>(AO,256, Wo,256,0, O1,256, M,256,256, bo, 0, inv);
    // h = relu([out || src] @ W1^T + b1) as two accumulating GEMMs
    gemm_kernel<<<dim3(1, M/128), 256>>>(O1,256,       W1,384,0,   H,128, M,128,256, nullptr, 0, nullptr);
    gemm_kernel<<<dim3(1, M/128), 256>>>(src_feat,128, W1,384,256, H,128, M,128,128, b1, GF_ACC|GF_RELU, nullptr);
    // final: h @ W2^T + b2
    gemm_kernel<<<dim3(1, M/128), 256>>>(H,128, W2,128,0, out,128, M,128,128, b2, 0, nullptr);
}

// ---------------- entry -----------------------------------------------------
extern "C" void kernel_launch(void* const* d_in, const int* in_sizes, int n_in,
                              void* d_out, int out_size)
{
    const float* node_feat   = (const float*)d_in[0];
    const float* memory      = (const float*)d_in[1];
    const float* edge_feat   = (const float*)d_in[2];
    const float* time_w      = (const float*)d_in[3];
    const float* time_b      = (const float*)d_in[4];
    const float* Wq          = (const float*)d_in[5];
    const float* bq          = (const float*)d_in[6];
    const float* Wk          = (const float*)d_in[7];
    const float* bk          = (const float*)d_in[8];
    const float* Wv          = (const float*)d_in[9];
    const float* bv          = (const float*)d_in[10];
    const float* Wo          = (const float*)d_in[11];
    const float* bo          = (const float*)d_in[12];
    const float* W1          = (const float*)d_in[13];
    const float* b1          = (const float*)d_in[14];
    const float* W2          = (const float*)d_in[15];
    const float* b2          = (const float*)d_in[16];
    const float* timestamps  = (const float*)d_in[17];
    const int*   src_nodes   = (const int*)d_in[18];
    const int*   neighbors1  = (const int*)d_in[19];
    const int*   edge_idx1   = (const int*)d_in[20];
    const float* edge_times1 = (const float*)d_in[21];
    const int*   neighbors2  = (const int*)d_in[22];
    const int*   edge_idx2   = (const int*)d_in[23];
    const float* edge_times2 = (const float*)d_in[24];

    float *keyv,*Kp,*Vp,*E1,*S,*Qb,*AO,*O1,*H,*NL1,*SL1,*cq; int* inv;
    cudaGetSymbolAddress((void**)&keyv, g_keyv);
    cudaGetSymbolAddress((void**)&Kp,   g_Kp);
    cudaGetSymbolAddress((void**)&Vp,   g_Vp);
    cudaGetSymbolAddress((void**)&E1,   g_E1);
    cudaGetSymbolAddress((void**)&S,    g_S);
    cudaGetSymbolAddress((void**)&Qb,   g_Q);
    cudaGetSymbolAddress((void**)&AO,   g_AO);
    cudaGetSymbolAddress((void**)&O1,   g_O1);
    cudaGetSymbolAddress((void**)&H,    g_H);
    cudaGetSymbolAddress((void**)&NL1,  g_NL1);
    cudaGetSymbolAddress((void**)&SL1,  g_SL1);
    cudaGetSymbolAddress((void**)&cq,   g_cq);
    cudaGetSymbolAddress((void**)&inv,  g_inv);

    // param-set pointers
    const float *Wq0=Wq,            *Wq1=Wq+256*256;
    const float *Wk0=Wk,            *Wk1=Wk+256*384;
    const float *Wv0=Wv,            *Wv1=Wv+256*384;
    const float *Wo0=Wo,            *Wo1=Wo+256*256;
    const float *W10=W1,            *W11=W1+128*384;
    const float *W20=W2,            *W21=W2+128*128;
    const float *bk0=bk, *bk1=bk+256, *bv0=bv, *bv1=bv+256;
    const float *bo0=bo, *bo1=bo+256, *b10=b1, *b11=b1+128;
    const float *b20=b2, *b21=b2+128;

    // stage 0: base embeddings + constant query parts
    gather_emb_kernel<<<M_HOP2, 128>>>(node_feat, memory, neighbors1, E1, M_HOP2);
    gather_emb_kernel<<<N_B,    128>>>(node_feat, memory, src_nodes,  S,  N_B);
    const_q_kernel<<<2, 256>>>(Wq, bq, time_b, cq);

    // stage 1: layer-1 embedding of flattened first-hop neighbors (params p0)
    run_layer(M_HOP2, E1, neighbors2, nullptr, edge_idx2, edge_times2,
              timestamps, N_K,
              node_feat, memory, edge_feat, time_w, time_b,
              Wq0, cq, Wk0, bk0, Wv0, bv0, Wo0, bo0, W10, b10, W20, b20,
              keyv, Kp, Vp, Qb, AO, O1, H, inv, NL1);

    // stage 2: layer-1 embedding of src nodes (params p0)
    run_layer(N_B, S, neighbors1, nullptr, edge_idx1, edge_times1,
              timestamps, 1,
              node_feat, memory, edge_feat, time_w, time_b,
              Wq0, cq, Wk0, bk0, Wv0, bv0, Wo0, bo0, W10, b10, W20, b20,
              keyv, Kp, Vp, Qb, AO, O1, H, inv, SL1);

    // stage 3: layer-2 aggregation (params p1), neighbor feats = neigh_l1
    run_layer(N_B, SL1, neighbors1, NL1, edge_idx1, edge_times1,
              timestamps, 1,
              node_feat, memory, edge_feat, time_w, time_b,
              Wq1, cq + N_QD, Wk1, bk1, Wv1, bv1, Wo1, bo1, W11, b11, W21, b21,
              keyv, Kp, Vp, Qb, AO, O1, H, inv, (float*)d_out);
}

// round 2
// speedup vs baseline: 3.5688x; 3.5688x over previous
#include <cuda_runtime.h>
#include <cuda_bf16.h>
#include <math.h>
#include <stdint.h>

#define N_B   8192
#define N_K   10
#define N_D   128
#define N_QD  256
#define N_KD  384
#define M_HOP2 (N_B * N_K)          // 81920
#define P_HOP2 (M_HOP2 * N_K)       // 819200

typedef __nv_bfloat16 bf16;

// ---------------- scratch (static __device__ globals; no allocs) ------------
__device__ bf16  g_kv_h [(size_t)P_HOP2 * N_KD];
__device__ bf16  g_kv_l [(size_t)P_HOP2 * N_KD];
__device__ float g_KV   [(size_t)P_HOP2 * 512];      // [Kp || Vp] fp32
__device__ float g_Q    [(size_t)M_HOP2 * N_QD];
__device__ bf16  g_ao_h [(size_t)M_HOP2 * N_QD];
__device__ bf16  g_ao_l [(size_t)M_HOP2 * N_QD];
__device__ bf16  g_cat_h[(size_t)M_HOP2 * N_KD];     // [Wo-out || src] bf16-hi
__device__ bf16  g_cat_l[(size_t)M_HOP2 * N_KD];
__device__ bf16  g_h_h  [(size_t)M_HOP2 * N_D];
__device__ bf16  g_h_l  [(size_t)M_HOP2 * N_D];
__device__ float g_NL1  [(size_t)M_HOP2 * N_D];
__device__ int   g_inv  [M_HOP2];
__device__ float g_cq   [2 * N_QD];
__device__ float g_bkv  [2 * 512];
// split weights
__device__ bf16 g_wkv_h[2*512*384], g_wkv_l[2*512*384];
__device__ bf16 g_wq_h [2*256*256], g_wq_l [2*256*256];
__device__ bf16 g_wo_h [2*256*256], g_wo_l [2*256*256];
__device__ bf16 g_w1_h [2*128*384], g_w1_l [2*128*384];
__device__ bf16 g_w2_h [2*128*128], g_w2_l [2*128*128];

// ---------------- helpers ---------------------------------------------------
__device__ __forceinline__ void split2(float v, bf16& h, bf16& l) {
    h = __float2bfloat16(v);
    l = __float2bfloat16(v - __bfloat162float(h));
}

__global__ void split_kernel(const float* __restrict__ src,
                             bf16* __restrict__ hi, bf16* __restrict__ lo, int n)
{
    int i = blockIdx.x * blockDim.x + threadIdx.x;
    if (i >= n) return;
    split2(src[i], hi[i], lo[i]);
}

// gather emb0 into cat buffer at col 256 (ld = 384)
__global__ void gather_emb_kernel(const float* __restrict__ nf,
                                  const float* __restrict__ mem,
                                  const int* __restrict__ idx,
                                  bf16* __restrict__ dh, bf16* __restrict__ dl, int n)
{
    int r = blockIdx.x;
    if (r >= n) return;
    int t = threadIdx.x;
    size_t s = (size_t)idx[r] * N_D + t;
    float v = nf[s] + mem[s];
    size_t o = (size_t)r * N_KD + 256 + t;
    split2(v, dh[o], dl[o]);
}

// keyv builder: [emb || edge_feat || cos(dt*w+b)] -> bf16 hi/lo
__global__ void build_keyv_kernel(const int* __restrict__ neigh,
                                  const int* __restrict__ eidx,
                                  const float* __restrict__ etime,
                                  const float* __restrict__ ts, int ts_div,
                                  const float* __restrict__ nf,
                                  const float* __restrict__ mem,
                                  const float* __restrict__ ef,
                                  const float* __restrict__ dense_neigh,
                                  const float* __restrict__ tw,
                                  const float* __restrict__ tb,
                                  bf16* __restrict__ kh, bf16* __restrict__ kl,
                                  int Mrows)
{
    int r = blockIdx.x;
    if (r >= Mrows) return;
    int t = threadIdx.x;       // 128
    float v0;
    if (dense_neigh) v0 = dense_neigh[(size_t)r * N_D + t];
    else { size_t s = (size_t)neigh[r] * N_D + t; v0 = nf[s] + mem[s]; }
    float v1 = ef[(size_t)eidx[r] * N_D + t];
    int m = r / N_K;
    float dd = ts[m / ts_div] - etime[r];
    float v2 = cosf(__fadd_rn(__fmul_rn(dd, tw[t]), tb[t]));
    size_t o = (size_t)r * N_KD;
    split2(v0, kh[o + t],       kl[o + t]);
    split2(v1, kh[o + 128 + t], kl[o + 128 + t]);
    split2(v2, kh[o + 256 + t], kl[o + 256 + t]);
}

// cq[j] = bq[j] + sum_t cos(tb[t]) * Wq[j,128+t]
__global__ void const_q_kernel(const float* __restrict__ Wq,
                               const float* __restrict__ bq,
                               const float* __restrict__ tb,
                               float* __restrict__ cq)
{
    __shared__ float ct[128];
    int p = blockIdx.x, j = threadIdx.x;
    if (j < 128) ct[j] = cosf(tb[j]);
    __syncthreads();
    const float* W = Wq + (size_t)p * N_QD * N_QD;
    float s = bq[p * N_QD + j];
    #pragma unroll 4
    for (int t = 0; t < 128; t++) s = fmaf(ct[t], W[(size_t)j * N_QD + 128 + t], s);
    cq[p * N_QD + j] = s;
}

// ---------------- bf16-split tensor-core GEMM -------------------------------
// C[M,N] = (Ah+Al)[M,Kd] @ (Wh+Wl)[N,Kd]^T  (al*bl term omitted; fp32 accum)
#define GF_RELU 1
#define SMS  40                  // smem row stride (bf16 elements), conflict-free for ldmatrix
#define MATB (128 * SMS * 2)     // bytes per matrix buffer (10240)
#define STGB (4 * MATB)          // bytes per double-buffer stage (40960)

__device__ __forceinline__ void cpa16(uint32_t s, const void* g) {
    asm volatile("cp.async.cg.shared.global [%0], [%1], 16;\n" :: "r"(s), "l"(g));
}
__device__ __forceinline__ void ldm4(uint32_t* r, uint32_t a) {
    asm volatile("ldmatrix.sync.aligned.m8n8.x4.shared.b16 {%0,%1,%2,%3},[%4];\n"
                 : "=r"(r[0]), "=r"(r[1]), "=r"(r[2]), "=r"(r[3]) : "r"(a));
}
__device__ __forceinline__ void mmabf(float* d, const uint32_t* a, uint32_t b0, uint32_t b1) {
    asm volatile("mma.sync.aligned.m16n8k16.row.col.f32.bf16.bf16.f32 "
                 "{%0,%1,%2,%3},{%4,%5,%6,%7},{%8,%9},{%0,%1,%2,%3};\n"
                 : "+f"(d[0]), "+f"(d[1]), "+f"(d[2]), "+f"(d[3])
                 : "r"(a[0]), "r"(a[1]), "r"(a[2]), "r"(a[3]), "r"(b0), "r"(b1));
}

__device__ __forceinline__ void issue_chunk(uint32_t sw, uint32_t bufofs,
    const bf16* Ah, const bf16* Al, size_t ga,
    const bf16* Wh, const bf16* Wl, size_t gw)
{
    uint32_t s0 = sw + bufofs;
    cpa16(s0,            Ah + ga); cpa16(s0 + 32,            Ah + ga + 16);
    cpa16(s0 + MATB,     Al + ga); cpa16(s0 + MATB + 32,     Al + ga + 16);
    cpa16(s0 + 2*MATB,   Wh + gw); cpa16(s0 + 2*MATB + 32,   Wh + gw + 16);
    cpa16(s0 + 3*MATB,   Wl + gw); cpa16(s0 + 3*MATB + 32,   Wl + gw + 16);
    asm volatile("cp.async.commit_group;\n");
}

__global__ __launch_bounds__(256) void mma_gemm(
    const bf16* __restrict__ Ah, const bf16* __restrict__ Al, int lda,
    const bf16* __restrict__ Wh, const bf16* __restrict__ Wl, int ldw,
    int Kd,
    const float* __restrict__ bias,
    float* __restrict__ Cf, int ldcf,
    bf16* __restrict__ Oh, bf16* __restrict__ Ol, int ldo,
    const int* __restrict__ zmask, int flags)
{
    extern __shared__ __align__(16) char smem_raw[];
    uint32_t sb = (uint32_t)__cvta_generic_to_shared(smem_raw);
    int tid = threadIdx.x;
    int m0 = blockIdx.y * 128, n0 = blockIdx.x * 128;
    int lane = tid & 31, wid = tid >> 5;
    int wm = wid & 1, wn = wid >> 1;   // warp tile 64x32

    float d[4][4][4];
    #pragma unroll
    for (int i = 0; i < 4; i++)
        #pragma unroll
        for (int j = 0; j < 4; j++)
            #pragma unroll
            for (int r = 0; r < 4; r++) d[i][j][r] = 0.f;

    int row = tid >> 1;
    int ce  = (tid & 1) << 3;
    size_t ga0 = (size_t)(m0 + row) * lda + ce;
    size_t gw0 = (size_t)(n0 + row) * ldw + ce;
    uint32_t sw = sb + (uint32_t)(row * SMS + ce) * 2;

    int nch = Kd >> 5;
    issue_chunk(sw, 0, Ah, Al, ga0, Wh, Wl, gw0);

    for (int c = 0; c < nch; c++) {
        if (c + 1 < nch) {
            int k0 = (c + 1) << 5;
            issue_chunk(sw, (uint32_t)((c + 1) & 1) * STGB, Ah, Al, ga0 + k0, Wh, Wl, gw0 + k0);
            asm volatile("cp.async.wait_group 1;\n");
        } else {
            asm volatile("cp.async.wait_group 0;\n");
        }
        __syncthreads();

        uint32_t base = sb + (uint32_t)(c & 1) * STGB;
        #pragma unroll
        for (int h = 0; h < 2; h++) {
            uint32_t ah[4][4], al[4][4], bh[2][4], bl[2][4];
            int colA = (h << 4) + ((lane >> 4) << 3);
            #pragma unroll
            for (int mi = 0; mi < 4; mi++) {
                int r_ = wm * 64 + mi * 16 + (lane & 15);
                uint32_t ad = base + (uint32_t)(r_ * SMS + colA) * 2;
                ldm4(ah[mi], ad);
                ldm4(al[mi], ad + MATB);
            }
            #pragma unroll
            for (int nj2 = 0; nj2 < 2; nj2++) {
                int r_ = wn * 32 + nj2 * 16 + (lane & 7) + (((lane >> 3) & 1) << 3);
                uint32_t bd = base + 2 * MATB + (uint32_t)(r_ * SMS + colA) * 2;
                ldm4(bh[nj2], bd);
                ldm4(bl[nj2], bd + MATB);
            }
            // three passes, 16 independent mma between accumulator reuse
            #pragma unroll
            for (int mi = 0; mi < 4; mi++)
                #pragma unroll
                for (int nj = 0; nj < 4; nj++)
                    mmabf(d[mi][nj], ah[mi], bh[nj >> 1][nj & 1], bh[nj >> 1][(nj & 1) + 2]);
            #pragma unroll
            for (int mi = 0; mi < 4; mi++)
                #pragma unroll
                for (int nj = 0; nj < 4; nj++)
                    mmabf(d[mi][nj], ah[mi], bl[nj >> 1][nj & 1], bl[nj >> 1][(nj & 1) + 2]);
            #pragma unroll
            for (int mi = 0; mi < 4; mi++)
                #pragma unroll
                for (int nj = 0; nj < 4; nj++)
                    mmabf(d[mi][nj], al[mi], bh[nj >> 1][nj & 1], bh[nj >> 1][(nj & 1) + 2]);
        }
        __syncthreads();
    }

    // epilogue
    int gr = lane >> 2, tg = lane & 3;
    #pragma unroll
    for (int mi = 0; mi < 4; mi++) {
        int mb = m0 + wm * 64 + mi * 16 + gr;
        #pragma unroll
        for (int half = 0; half < 2; half++) {
            int m = mb + half * 8;
            bool zero = (zmask != nullptr) && (zmask[m] != 0);
            #pragma unroll
            for (int nj = 0; nj < 4; nj++) {
                int n = n0 + wn * 32 + nj * 8 + tg * 2;
                float v0 = d[mi][nj][half * 2 + 0];
                float v1 = d[mi][nj][half * 2 + 1];
                if (bias) { v0 += bias[n]; v1 += bias[n + 1]; }
                if (flags & GF_RELU) { v0 = fmaxf(v0, 0.f); v1 = fmaxf(v1, 0.f); }
                if (zero) { v0 = 0.f; v1 = 0.f; }
                if (Cf) *(float2*)&Cf[(size_t)m * ldcf + n] = make_float2(v0, v1);
                if (Oh) {
                    __nv_bfloat162 hh, ll;
                    split2(v0, hh.x, ll.x);
                    split2(v1, hh.y, ll.y);
                    *(__nv_bfloat162*)&Oh[(size_t)m * ldo + n] = hh;
                    *(__nv_bfloat162*)&Ol[(size_t)m * ldo + n] = ll;
                }
            }
        }
    }
}

// ---------------- attention core: one warp per (row, head) ------------------
__global__ void attn_kernel(const float* __restrict__ Q,
                            const float* __restrict__ KV,
                            const int* __restrict__ neigh,
                            bf16* __restrict__ AOh, bf16* __restrict__ AOl,
                            int* __restrict__ inv, int M)
{
    int gw = (int)((blockIdx.x * (size_t)blockDim.x + threadIdx.x) >> 5);
    int lane = threadIdx.x & 31;
    if (gw >= M * 2) return;
    int m = gw >> 1, h = gw & 1;
    const float SC = 0.08838834764831843f;   // 1/sqrt(128)

    float4 q = *(const float4*)&Q[(size_t)m * N_QD + h * 128 + lane * 4];

    bool msk[N_K]; bool allm = true;
    #pragma unroll
    for (int k = 0; k < N_K; k++) {
        msk[k] = (neigh[m * N_K + k] == 0);
        allm = allm && msk[k];
    }

    float sc[N_K];
    #pragma unroll
    for (int k = 0; k < N_K; k++) {
        float4 kv = *(const float4*)&KV[((size_t)m * N_K + k) * 512 + h * 128 + lane * 4];
        float p = q.x*kv.x + q.y*kv.y + q.z*kv.z + q.w*kv.w;
        #pragma unroll
        for (int o = 16; o; o >>= 1) p += __shfl_xor_sync(0xffffffffu, p, o);
        float s = p * SC;
        bool mk = msk[k] && !(allm && k == 0);
        sc[k] = mk ? -1e9f : s;
    }
    float mx = sc[0];
    #pragma unroll
    for (int k = 1; k < N_K; k++) mx = fmaxf(mx, sc[k]);
    float sum = 0.f;
    #pragma unroll
    for (int k = 0; k < N_K; k++) { sc[k] = expf(sc[k] - mx); sum += sc[k]; }
    float rinv = 1.f / sum;

    float4 o = make_float4(0.f, 0.f, 0.f, 0.f);
    #pragma unroll
    for (int k = 0; k < N_K; k++) {
        float w = sc[k] * rinv;
        float4 v = *(const float4*)&KV[((size_t)m * N_K + k) * 512 + 256 + h * 128 + lane * 4];
        o.x = fmaf(w, v.x, o.x); o.y = fmaf(w, v.y, o.y);
        o.z = fmaf(w, v.z, o.z); o.w = fmaf(w, v.w, o.w);
    }
    size_t ob = (size_t)m * N_QD + h * 128 + lane * 4;
    __nv_bfloat162 h0, l0, h1, l1;
    split2(o.x, h0.x, l0.x); split2(o.y, h0.y, l0.y);
    split2(o.z, h1.x, l1.x); split2(o.w, h1.y, l1.y);
    *(__nv_bfloat162*)&AOh[ob]     = h0;  *(__nv_bfloat162*)&AOl[ob]     = l0;
    *(__nv_bfloat162*)&AOh[ob + 2] = h1;  *(__nv_bfloat162*)&AOl[ob + 2] = l1;
    if (h == 0 && lane == 0) inv[m] = allm ? 1 : 0;
}

// ---------------- one temporal attention layer ------------------------------
struct Ptrs {
    bf16 *kvh, *kvl, *aoh, *aol, *cath, *catl, *hh, *hl;
    float *KV, *Qb; int* inv;
    bf16 *wkvh, *wkvl, *wqh, *wql, *woh, *wol, *w1h, *w1l, *w2h, *w2l;
    float *cq, *bkv;
};

static void run_layer(const Ptrs& P, int p, int M,
                      const int* neigh, const float* dense_neigh,
                      const int* eidx, const float* etime,
                      const float* ts, int ts_div,
                      const float* nf, const float* mem, const float* ef,
                      const float* tw, const float* tb,
                      const float* bo, const float* b1, const float* b2,
                      float* outCf, bf16* outOh, bf16* outOl, int out_ldo)
{
    int MK = M * N_K;
    const int SMEM = 2 * STGB;
    build_keyv_kernel<<<MK, 128>>>(neigh, eidx, etime, ts, ts_div, nf, mem, ef,
                                   dense_neigh, tw, tb, P.kvh, P.kvl, MK);
    // Q = src @ Wq[:,:128]^T + cq
    mma_gemm<<<dim3(2, M/128), 256, SMEM>>>(
        P.cath + 256, P.catl + 256, 384,
        P.wqh + (size_t)p*256*256, P.wql + (size_t)p*256*256, 256, 128,
        P.cq + p*256, P.Qb, 256, nullptr, nullptr, 0, nullptr, 0);
    // [Kp||Vp] = keyv @ WKV^T + bkv
    mma_gemm<<<dim3(4, MK/128), 256, SMEM>>>(
        P.kvh, P.kvl, 384,
        P.wkvh + (size_t)p*512*384, P.wkvl + (size_t)p*512*384, 384, 384,
        P.bkv + p*512, P.KV, 512, nullptr, nullptr, 0, nullptr, 0);
    attn_kernel<<<(M*2*32 + 255)/256, 256>>>(P.Qb, P.KV, neigh, P.aoh, P.aol, P.inv, M);
    // Wo projection -> cat cols 0..255 (zeroed on invalid rows)
    mma_gemm<<<dim3(2, M/128), 256, SMEM>>>(
        P.aoh, P.aol, 256,
        P.woh + (size_t)p*256*256, P.wol + (size_t)p*256*256, 256, 256,
        bo + p*256, nullptr, 0, P.cath, P.catl, 384, P.inv, 0);
    // h = relu(cat @ W1^T + b1)
    mma_gemm<<<dim3(1, M/128), 256, SMEM>>>(
        P.cath, P.catl, 384,
        P.w1h + (size_t)p*128*384, P.w1l + (size_t)p*128*384, 384, 384,
        b1 + p*128, nullptr, 0, P.hh, P.hl, 128, nullptr, GF_RELU);
    // out = h @ W2^T + b2
    mma_gemm<<<dim3(1, M/128), 256, SMEM>>>(
        P.hh, P.hl, 128,
        P.w2h + (size_t)p*128*128, P.w2l + (size_t)p*128*128, 128, 128,
        b2 + p*128, outCf, 128, outOh, outOl, out_ldo, nullptr, 0);
}

// ---------------- entry -----------------------------------------------------
extern "C" void kernel_launch(void* const* d_in, const int* in_sizes, int n_in,
                              void* d_out, int out_size)
{
    const float* node_feat   = (const float*)d_in[0];
    const float* memory      = (const float*)d_in[1];
    const float* edge_feat   = (const float*)d_in[2];
    const float* time_w      = (const float*)d_in[3];
    const float* time_b      = (const float*)d_in[4];
    const float* Wq          = (const float*)d_in[5];
    const float* bq          = (const float*)d_in[6];
    const float* Wk          = (const float*)d_in[7];
    const float* bk          = (const float*)d_in[8];
    const float* Wv          = (const float*)d_in[9];
    const float* bv          = (const float*)d_in[10];
    const float* Wo          = (const float*)d_in[11];
    const float* bo          = (const float*)d_in[12];
    const float* W1          = (const float*)d_in[13];
    const float* b1          = (const float*)d_in[14];
    const float* W2          = (const float*)d_in[15];
    const float* b2          = (const float*)d_in[16];
    const float* timestamps  = (const float*)d_in[17];
    const int*   src_nodes   = (const int*)d_in[18];
    const int*   neighbors1  = (const int*)d_in[19];
    const int*   edge_idx1   = (const int*)d_in[20];
    const float* edge_times1 = (const float*)d_in[21];
    const int*   neighbors2  = (const int*)d_in[22];
    const int*   edge_idx2   = (const int*)d_in[23];
    const float* edge_times2 = (const float*)d_in[24];

    cudaFuncSetAttribute(mma_gemm, cudaFuncAttributeMaxDynamicSharedMemorySize, 2 * STGB);

    Ptrs P; float* NL1; float* cq; float* bkv;
    cudaGetSymbolAddress((void**)&P.kvh,  g_kv_h);
    cudaGetSymbolAddress((void**)&P.kvl,  g_kv_l);
    cudaGetSymbolAddress((void**)&P.KV,   g_KV);
    cudaGetSymbolAddress((void**)&P.Qb,   g_Q);
    cudaGetSymbolAddress((void**)&P.aoh,  g_ao_h);
    cudaGetSymbolAddress((void**)&P.aol,  g_ao_l);
    cudaGetSymbolAddress((void**)&P.cath, g_cat_h);
    cudaGetSymbolAddress((void**)&P.catl, g_cat_l);
    cudaGetSymbolAddress((void**)&P.hh,   g_h_h);
    cudaGetSymbolAddress((void**)&P.hl,   g_h_l);
    cudaGetSymbolAddress((void**)&NL1,    g_NL1);
    cudaGetSymbolAddress((void**)&P.inv,  g_inv);
    cudaGetSymbolAddress((void**)&cq,     g_cq);
    cudaGetSymbolAddress((void**)&bkv,    g_bkv);
    cudaGetSymbolAddress((void**)&P.wkvh, g_wkv_h);
    cudaGetSymbolAddress((void**)&P.wkvl, g_wkv_l);
    cudaGetSymbolAddress((void**)&P.wqh,  g_wq_h);
    cudaGetSymbolAddress((void**)&P.wql,  g_wq_l);
    cudaGetSymbolAddress((void**)&P.woh,  g_wo_h);
    cudaGetSymbolAddress((void**)&P.wol,  g_wo_l);
    cudaGetSymbolAddress((void**)&P.w1h,  g_w1_h);
    cudaGetSymbolAddress((void**)&P.w1l,  g_w1_l);
    cudaGetSymbolAddress((void**)&P.w2h,  g_w2_h);
    cudaGetSymbolAddress((void**)&P.w2l,  g_w2_l);
    P.cq = cq; P.bkv = bkv;

    // ---- weight conversion (bf16 hi/lo split) + stacked K/V weights
    const int nkv = 256 * 384;
    split_kernel<<<(nkv+255)/256, 256>>>(Wk,       P.wkvh,             P.wkvl,             nkv);
    split_kernel<<<(nkv+255)/256, 256>>>(Wv,       P.wkvh + nkv,       P.wkvl + nkv,       nkv);
    split_kernel<<<(nkv+255)/256, 256>>>(Wk + nkv, P.wkvh + 2*nkv,     P.wkvl + 2*nkv,     nkv);
    split_kernel<<<(nkv+255)/256, 256>>>(Wv + nkv, P.wkvh + 3*nkv,     P.wkvl + 3*nkv,     nkv);
    split_kernel<<<(2*256*256+255)/256, 256>>>(Wq, P.wqh, P.wql, 2*256*256);
    split_kernel<<<(2*256*256+255)/256, 256>>>(Wo, P.woh, P.wol, 2*256*256);
    split_kernel<<<(2*128*384+255)/256, 256>>>(W1, P.w1h, P.w1l, 2*128*384);
    split_kernel<<<(2*128*128+255)/256, 256>>>(W2, P.w2h, P.w2l, 2*128*128);
    cudaMemcpyAsync(bkv + 0,   bk,       256*4, cudaMemcpyDeviceToDevice);
    cudaMemcpyAsync(bkv + 256, bv,       256*4, cudaMemcpyDeviceToDevice);
    cudaMemcpyAsync(bkv + 512, bk + 256, 256*4, cudaMemcpyDeviceToDevice);
    cudaMemcpyAsync(bkv + 768, bv + 256, 256*4, cudaMemcpyDeviceToDevice);
    const_q_kernel<<<2, 256>>>(Wq, bq, time_b, cq);

    // ---- stage 1: layer-1 embedding of flattened first-hop neighbors (p0)
    gather_emb_kernel<<<M_HOP2, 128>>>(node_feat, memory, neighbors1, P.cath, P.catl, M_HOP2);
    run_layer(P, 0, M_HOP2, neighbors2, nullptr, edge_idx2, edge_times2,
              timestamps, N_K, node_feat, memory, edge_feat, time_w, time_b,
              bo, b1, b2, NL1, nullptr, nullptr, 0);

    // ---- stage 2: layer-1 embedding of src nodes (p0); SL1 -> cat col 256
    gather_emb_kernel<<<N_B, 128>>>(node_feat, memory, src_nodes, P.cath, P.catl, N_B);
    run_layer(P, 0, N_B, neighbors1, nullptr, edge_idx1, edge_times1,
              timestamps, 1, node_feat, memory, edge_feat, time_w, time_b,
              bo, b1, b2, nullptr, P.cath + 256, P.catl + 256, 384);

    // ---- stage 3: layer-2 aggregation (p1), neighbor feats = NL1
    run_layer(P, 1, N_B, neighbors1, NL1, edge_idx1, edge_times1,
              timestamps, 1, node_feat, memory, edge_feat, time_w, time_b,
              bo, b1, b2, (float*)d_out, nullptr, nullptr, 0);
}

// round 4
// speedup vs baseline: 4.5202x; 1.2666x over previous
#include <cuda_runtime.h>
#include <cuda_fp16.h>
#include <math.h>
#include <stdint.h>

#define N_B   8192
#define N_K   10
#define N_D   128
#define N_QD  256
#define N_KD  384
#define M_HOP2 (N_B * N_K)          // 81920
#define P_HOP2 (M_HOP2 * N_K)       // 819200

// ---------------- scratch (static __device__ globals; no allocs) ------------
__device__ __half g_kv_h [(size_t)P_HOP2 * N_KD];
__device__ __half g_kv_l [(size_t)P_HOP2 * N_KD];
__device__ float  g_KV   [(size_t)P_HOP2 * 512];      // [Kp || Vp] fp32
__device__ float  g_Q    [(size_t)M_HOP2 * N_QD];
__device__ __half g_ao_h [(size_t)M_HOP2 * N_QD];
__device__ __half g_ao_l [(size_t)M_HOP2 * N_QD];
__device__ __half g_cat_h[(size_t)M_HOP2 * N_KD];     // [Wo-out || src] fp16-hi
__device__ __half g_cat_l[(size_t)M_HOP2 * N_KD];
__device__ __half g_h_h  [(size_t)M_HOP2 * N_D];
__device__ __half g_h_l  [(size_t)M_HOP2 * N_D];
__device__ float  g_NL1  [(size_t)M_HOP2 * N_D];
__device__ int    g_inv  [M_HOP2];
__device__ float  g_cq   [2 * N_QD];
__device__ float  g_bkv  [2 * 512];
// fp16 weights (hi only)
__device__ __half g_wkv[2*512*384];
__device__ __half g_wq [2*256*256];
__device__ __half g_wo [2*256*256];
__device__ __half g_w1 [2*128*384];
__device__ __half g_w2 [2*128*128];

// ---------------- helpers ---------------------------------------------------
__device__ __forceinline__ void split2h(float v, __half& h, __half& l) {
    h = __float2half_rn(v);
    l = __float2half_rn(v - __half2float(h));
}

// ---------------- merged weight prep (1 launch) -----------------------------
__global__ void prep_weights(const float* __restrict__ Wq, const float* __restrict__ Wo,
                             const float* __restrict__ W1, const float* __restrict__ W2,
                             const float* __restrict__ Wk, const float* __restrict__ Wv,
                             const float* __restrict__ bk, const float* __restrict__ bv,
                             __half* __restrict__ wq, __half* __restrict__ wo,
                             __half* __restrict__ w1, __half* __restrict__ w2,
                             __half* __restrict__ wkv, float* __restrict__ bkv)
{
    int i = blockIdx.x * blockDim.x + threadIdx.x;
    if (i < 131072) { wq[i] = __float2half_rn(Wq[i]); return; }
    i -= 131072;
    if (i < 131072) { wo[i] = __float2half_rn(Wo[i]); return; }
    i -= 131072;
    if (i < 98304)  { w1[i] = __float2half_rn(W1[i]); return; }
    i -= 98304;
    if (i < 32768)  { w2[i] = __float2half_rn(W2[i]); return; }
    i -= 32768;
    if (i < 2*512*384) {
        int p = i / (512*384), r = i % (512*384);
        int n = r / 384, k = r % 384;
        float v = (n < 256) ? Wk[(size_t)p*256*384 + (size_t)n*384 + k]
                            : Wv[(size_t)p*256*384 + (size_t)(n-256)*384 + k];
        wkv[i] = __float2half_rn(v);
        return;
    }
    i -= 2*512*384;
    if (i < 1024) {
        int p = i >> 9, j = i & 511;
        bkv[i] = (j < 256) ? bk[p*256 + j] : bv[p*256 + (j - 256)];
    }
}

// cq[j] = bq[j] + sum_t cos(tb[t]) * Wq[j,128+t]   (fp32, exact path)
__global__ void const_q_kernel(const float* __restrict__ Wq,
                               const float* __restrict__ bq,
                               const float* __restrict__ tb,
                               float* __restrict__ cq)
{
    __shared__ float ct[128];
    int p = blockIdx.x, j = threadIdx.x;
    if (j < 128) ct[j] = cosf(tb[j]);
    __syncthreads();
    const float* W = Wq + (size_t)p * N_QD * N_QD;
    float s = bq[p * N_QD + j];
    #pragma unroll 4
    for (int t = 0; t < 128; t++) s = fmaf(ct[t], W[(size_t)j * N_QD + 128 + t], s);
    cq[p * N_QD + j] = s;
}

// gather emb0 into cat buffer at col 256 (ld = 384)
__global__ void gather_emb_kernel(const float* __restrict__ nf,
                                  const float* __restrict__ mem,
                                  const int* __restrict__ idx,
                                  __half* __restrict__ dh, __half* __restrict__ dl, int n)
{
    int r = blockIdx.x;
    if (r >= n) return;
    int t = threadIdx.x;
    size_t s = (size_t)idx[r] * N_D + t;
    float v = nf[s] + mem[s];
    size_t o = (size_t)r * N_KD + 256 + t;
    split2h(v, dh[o], dl[o]);
}

// keyv builder: [emb || edge_feat || cos(dt*w+b)] -> fp16 hi/lo
__global__ void build_keyv_kernel(const int* __restrict__ neigh,
                                  const int* __restrict__ eidx,
                                  const float* __restrict__ etime,
                                  const float* __restrict__ ts, int ts_div,
                                  const float* __restrict__ nf,
                                  const float* __restrict__ mem,
                                  const float* __restrict__ ef,
                                  const float* __restrict__ dense_neigh,
                                  const float* __restrict__ tw,
                                  const float* __restrict__ tb,
                                  __half* __restrict__ kh, __half* __restrict__ kl,
                                  int Mrows)
{
    int r = blockIdx.x;
    if (r >= Mrows) return;
    int t = threadIdx.x;       // 128
    float v0;
    if (dense_neigh) v0 = dense_neigh[(size_t)r * N_D + t];
    else { size_t s = (size_t)neigh[r] * N_D + t; v0 = nf[s] + mem[s]; }
    float v1 = ef[(size_t)eidx[r] * N_D + t];
    int m = r / N_K;
    float dd = ts[m / ts_div] - etime[r];
    float v2 = cosf(__fadd_rn(__fmul_rn(dd, tw[t]), tb[t]));
    size_t o = (size_t)r * N_KD;
    split2h(v0, kh[o + t],       kl[o + t]);
    split2h(v1, kh[o + 128 + t], kl[o + 128 + t]);
    split2h(v2, kh[o + 256 + t], kl[o + 256 + t]);
}

// ---------------- fp16 2-pass tensor-core GEMM ------------------------------
// C[M,N] = (Ah+Al)[M,Kd] @ Wh[N,Kd]^T   (A exact to ~2^-22, W fp16; fp32 accum)
#define GF_RELU 1
#define SMS  40                  // smem row stride (halves), conflict-free ldmatrix
#define MATB (128 * SMS * 2)     // bytes per matrix buffer (10240)
#define STGB (3 * MATB)          // bytes per stage: Ah, Al, Wh (30720)
#define NSTG 3
#define GSMEM (NSTG * STGB)      // 92160

__device__ __forceinline__ void cpa16(uint32_t s, const void* g) {
    asm volatile("cp.async.cg.shared.global [%0], [%1], 16;\n" :: "r"(s), "l"(g));
}
__device__ __forceinline__ void ldm4(uint32_t* r, uint32_t a) {
    asm volatile("ldmatrix.sync.aligned.m8n8.x4.shared.b16 {%0,%1,%2,%3},[%4];\n"
                 : "=r"(r[0]), "=r"(r[1]), "=r"(r[2]), "=r"(r[3]) : "r"(a));
}
__device__ __forceinline__ void mmaf16(float* d, const uint32_t* a, uint32_t b0, uint32_t b1) {
    asm volatile("mma.sync.aligned.m16n8k16.row.col.f32.f16.f16.f32 "
                 "{%0,%1,%2,%3},{%4,%5,%6,%7},{%8,%9},{%0,%1,%2,%3};\n"
                 : "+f"(d[0]), "+f"(d[1]), "+f"(d[2]), "+f"(d[3])
                 : "r"(a[0]), "r"(a[1]), "r"(a[2]), "r"(a[3]), "r"(b0), "r"(b1));
}

__device__ __forceinline__ void issue_chunk(uint32_t sw, uint32_t bufofs,
    const __half* Ah, const __half* Al, size_t ga,
    const __half* Wh, size_t gw)
{
    uint32_t s0 = sw + bufofs;
    cpa16(s0,          Ah + ga); cpa16(s0 + 32,          Ah + ga + 16);
    cpa16(s0 + MATB,   Al + ga); cpa16(s0 + MATB + 32,   Al + ga + 16);
    cpa16(s0 + 2*MATB, Wh + gw); cpa16(s0 + 2*MATB + 32, Wh + gw + 16);
    asm volatile("cp.async.commit_group;\n");
}

__global__ __launch_bounds__(256, 2) void mma_gemm(
    const __half* __restrict__ Ah, const __half* __restrict__ Al, int lda,
    const __half* __restrict__ Wh, int ldw,
    int Kd,
    const float* __restrict__ bias,
    float* __restrict__ Cf, int ldcf,
    __half* __restrict__ Oh, __half* __restrict__ Ol, int ldo,
    const int* __restrict__ zmask, int flags)
{
    extern __shared__ __align__(16) char smem_raw[];
    uint32_t sb = (uint32_t)__cvta_generic_to_shared(smem_raw);
    int tid = threadIdx.x;
    int m0 = blockIdx.y * 128, n0 = blockIdx.x * 128;
    int lane = tid & 31, wid = tid >> 5;
    int wm = wid & 1, wn = wid >> 1;   // warp tile 64x32

    float d[4][4][4];
    #pragma unroll
    for (int i = 0; i < 4; i++)
        #pragma unroll
        for (int j = 0; j < 4; j++)
            #pragma unroll
            for (int r = 0; r < 4; r++) d[i][j][r] = 0.f;

    int row = tid >> 1;
    int ce  = (tid & 1) << 3;
    size_t ga0 = (size_t)(m0 + row) * lda + ce;
    size_t gw0 = (size_t)(n0 + row) * ldw + ce;
    uint32_t sw = sb + (uint32_t)(row * SMS + ce) * 2;

    int nch = Kd >> 5;
    issue_chunk(sw, 0, Ah, Al, ga0, Wh, gw0);
    if (nch > 1) issue_chunk(sw, STGB, Ah, Al, ga0 + 32, Wh, gw0 + 32);

    for (int c = 0; c < nch; c++) {
        if (c + 2 < nch) {
            int k0 = (c + 2) << 5;
            issue_chunk(sw, (uint32_t)((c + 2) % NSTG) * STGB, Ah, Al, ga0 + k0, Wh, gw0 + k0);
        }
        int issuedJ = (c + 2 < nch) ? c + 2 : nch - 1;
        int allow = issuedJ - c;
        if (allow >= 2)      asm volatile("cp.async.wait_group 2;\n" ::: "memory");
        else if (allow == 1) asm volatile("cp.async.wait_group 1;\n" ::: "memory");
        else                 asm volatile("cp.async.wait_group 0;\n" ::: "memory");
        __syncthreads();

        uint32_t base = sb + (uint32_t)(c % NSTG) * STGB;
        #pragma unroll
        for (int h = 0; h < 2; h++) {
            uint32_t ah[4][4], al[4][4], bh[2][4];
            int colA = (h << 4) + ((lane >> 4) << 3);
            #pragma unroll
            for (int mi = 0; mi < 4; mi++) {
                int r_ = wm * 64 + mi * 16 + (lane & 15);
                uint32_t ad = base + (uint32_t)(r_ * SMS + colA) * 2;
                ldm4(ah[mi], ad);
                ldm4(al[mi], ad + MATB);
            }
            #pragma unroll
            for (int nj2 = 0; nj2 < 2; nj2++) {
                int r_ = wn * 32 + nj2 * 16 + (lane & 7) + (((lane >> 3) & 1) << 3);
                uint32_t bd = base + 2 * MATB + (uint32_t)(r_ * SMS + colA) * 2;
                ldm4(bh[nj2], bd);
            }
            // two passes: ah*bh then al*bh (16 independent mma per pass)
            #pragma unroll
            for (int mi = 0; mi < 4; mi++)
                #pragma unroll
                for (int nj = 0; nj < 4; nj++)
                    mmaf16(d[mi][nj], ah[mi], bh[nj >> 1][nj & 1], bh[nj >> 1][(nj & 1) + 2]);
            #pragma unroll
            for (int mi = 0; mi < 4; mi++)
                #pragma unroll
                for (int nj = 0; nj < 4; nj++)
                    mmaf16(d[mi][nj], al[mi], bh[nj >> 1][nj & 1], bh[nj >> 1][(nj & 1) + 2]);
        }
        __syncthreads();
    }

    // epilogue
    int gr = lane >> 2, tg = lane & 3;
    #pragma unroll
    for (int mi = 0; mi < 4; mi++) {
        int mb = m0 + wm * 64 + mi * 16 + gr;
        #pragma unroll
        for (int half = 0; half < 2; half++) {
            int m = mb + half * 8;
            bool zero = (zmask != nullptr) && (zmask[m] != 0);
            #pragma unroll
            for (int nj = 0; nj < 4; nj++) {
                int n = n0 + wn * 32 + nj * 8 + tg * 2;
                float v0 = d[mi][nj][half * 2 + 0];
                float v1 = d[mi][nj][half * 2 + 1];
                if (bias) { v0 += bias[n]; v1 += bias[n + 1]; }
                if (flags & GF_RELU) { v0 = fmaxf(v0, 0.f); v1 = fmaxf(v1, 0.f); }
                if (zero) { v0 = 0.f; v1 = 0.f; }
                if (Cf) *(float2*)&Cf[(size_t)m * ldcf + n] = make_float2(v0, v1);
                if (Oh) {
                    __half2 hh, ll;
                    split2h(v0, hh.x, ll.x);
                    split2h(v1, hh.y, ll.y);
                    *(__half2*)&Oh[(size_t)m * ldo + n] = hh;
                    *(__half2*)&Ol[(size_t)m * ldo + n] = ll;
                }
            }
        }
    }
}

// ---------------- attention core: one warp per (row, head) ------------------
__global__ void attn_kernel(const float* __restrict__ Q,
                            const float* __restrict__ KV,
                            const int* __restrict__ neigh,
                            __half* __restrict__ AOh, __half* __restrict__ AOl,
                            int* __restrict__ inv, int M)
{
    int gw = (int)((blockIdx.x * (size_t)blockDim.x + threadIdx.x) >> 5);
    int lane = threadIdx.x & 31;
    if (gw >= M * 2) return;
    int m = gw >> 1, h = gw & 1;
    const float SC = 0.08838834764831843f;   // 1/sqrt(128)

    float4 q = *(const float4*)&Q[(size_t)m * N_QD + h * 128 + lane * 4];

    bool msk[N_K]; bool allm = true;
    #pragma unroll
    for (int k = 0; k < N_K; k++) {
        msk[k] = (neigh[m * N_K + k] == 0);
        allm = allm && msk[k];
    }

    float sc[N_K];
    #pragma unroll
    for (int k = 0; k < N_K; k++) {
        float4 kv = *(const float4*)&KV[((size_t)m * N_K + k) * 512 + h * 128 + lane * 4];
        float p = q.x*kv.x + q.y*kv.y + q.z*kv.z + q.w*kv.w;
        #pragma unroll
        for (int o = 16; o; o >>= 1) p += __shfl_xor_sync(0xffffffffu, p, o);
        float s = p * SC;
        bool mk = msk[k] && !(allm && k == 0);
        sc[k] = mk ? -1e9f : s;
    }
    float mx = sc[0];
    #pragma unroll
    for (int k = 1; k < N_K; k++) mx = fmaxf(mx, sc[k]);
    float sum = 0.f;
    #pragma unroll
    for (int k = 0; k < N_K; k++) { sc[k] = expf(sc[k] - mx); sum += sc[k]; }
    float rinv = 1.f / sum;

    float4 o = make_float4(0.f, 0.f, 0.f, 0.f);
    #pragma unroll
    for (int k = 0; k < N_K; k++) {
        float w = sc[k] * rinv;
        float4 v = *(const float4*)&KV[((size_t)m * N_K + k) * 512 + 256 + h * 128 + lane * 4];
        o.x = fmaf(w, v.x, o.x); o.y = fmaf(w, v.y, o.y);
        o.z = fmaf(w, v.z, o.z); o.w = fmaf(w, v.w, o.w);
    }
    size_t ob = (size_t)m * N_QD + h * 128 + lane * 4;
    __half2 h0, l0, h1, l1;
    split2h(o.x, h0.x, l0.x); split2h(o.y, h0.y, l0.y);
    split2h(o.z, h1.x, l1.x); split2h(o.w, h1.y, l1.y);
    *(__half2*)&AOh[ob]     = h0;  *(__half2*)&AOl[ob]     = l0;
    *(__half2*)&AOh[ob + 2] = h1;  *(__half2*)&AOl[ob + 2] = l1;
    if (h == 0 && lane == 0) inv[m] = allm ? 1 : 0;
}

// ---------------- one temporal attention layer ------------------------------
struct Ptrs {
    __half *kvh, *kvl, *aoh, *aol, *cath, *catl, *hh, *hl;
    float *KV, *Qb; int* inv;
    __half *wkv, *wq, *wo, *w1, *w2;
    float *cq, *bkv;
};

static void run_layer(const Ptrs& P, int p, int M,
                      const int* neigh, const float* dense_neigh,
                      const int* eidx, const float* etime,
                      const float* ts, int ts_div,
                      const float* nf, const float* mem, const float* ef,
                      const float* tw, const float* tb,
                      const float* bo, const float* b1, const float* b2,
                      float* outCf, __half* outOh, __half* outOl, int out_ldo)
{
    int MK = M * N_K;
    build_keyv_kernel<<<MK, 128>>>(neigh, eidx, etime, ts, ts_div, nf, mem, ef,
                                   dense_neigh, tw, tb, P.kvh, P.kvl, MK);
    // Q = src @ Wq[:,:128]^T + cq
    mma_gemm<<<dim3(2, M/128), 256, GSMEM>>>(
        P.cath + 256, P.catl + 256, 384,
        P.wq + (size_t)p*256*256, 256, 128,
        P.cq + p*256, P.Qb, 256, nullptr, nullptr, 0, nullptr, 0);
    // [Kp||Vp] = keyv @ WKV^T + bkv
    mma_gemm<<<dim3(4, MK/128), 256, GSMEM>>>(
        P.kvh, P.kvl, 384,
        P.wkv + (size_t)p*512*384, 384, 384,
        P.bkv + p*512, P.KV, 512, nullptr, nullptr, 0, nullptr, 0);
    attn_kernel<<<(M*2*32 + 255)/256, 256>>>(P.Qb, P.KV, neigh, P.aoh, P.aol, P.inv, M);
    // Wo projection -> cat cols 0..255 (zeroed on invalid rows)
    mma_gemm<<<dim3(2, M/128), 256, GSMEM>>>(
        P.aoh, P.aol, 256,
        P.wo + (size_t)p*256*256, 256, 256,
        bo + p*256, nullptr, 0, P.cath, P.catl, 384, P.inv, 0);
    // h = relu(cat @ W1^T + b1)
    mma_gemm<<<dim3(1, M/128), 256, GSMEM>>>(
        P.cath, P.catl, 384,
        P.w1 + (size_t)p*128*384, 384, 384,
        b1 + p*128, nullptr, 0, P.hh, P.hl, 128, nullptr, GF_RELU);
    // out = h @ W2^T + b2
    mma_gemm<<<dim3(1, M/128), 256, GSMEM>>>(
        P.hh, P.hl, 128,
        P.w2 + (size_t)p*128*128, 128, 128,
        b2 + p*128, outCf, 128, outOh, outOl, out_ldo, nullptr, 0);
}

// ---------------- entry -----------------------------------------------------
extern "C" void kernel_launch(void* const* d_in, const int* in_sizes, int n_in,
                              void* d_out, int out_size)
{
    const float* node_feat   = (const float*)d_in[0];
    const float* memory      = (const float*)d_in[1];
    const float* edge_feat   = (const float*)d_in[2];
    const float* time_w      = (const float*)d_in[3];
    const float* time_b      = (const float*)d_in[4];
    const float* Wq          = (const float*)d_in[5];
    const float* bq          = (const float*)d_in[6];
    const float* Wk          = (const float*)d_in[7];
    const float* bk          = (const float*)d_in[8];
    const float* Wv          = (const float*)d_in[9];
    const float* bv          = (const float*)d_in[10];
    const float* Wo          = (const float*)d_in[11];
    const float* bo          = (const float*)d_in[12];
    const float* W1          = (const float*)d_in[13];
    const float* b1          = (const float*)d_in[14];
    const float* W2          = (const float*)d_in[15];
    const float* b2          = (const float*)d_in[16];
    const float* timestamps  = (const float*)d_in[17];
    const int*   src_nodes   = (const int*)d_in[18];
    const int*   neighbors1  = (const int*)d_in[19];
    const int*   edge_idx1   = (const int*)d_in[20];
    const float* edge_times1 = (const float*)d_in[21];
    const int*   neighbors2  = (const int*)d_in[22];
    const int*   edge_idx2   = (const int*)d_in[23];
    const float* edge_times2 = (const float*)d_in[24];

    cudaFuncSetAttribute(mma_gemm, cudaFuncAttributeMaxDynamicSharedMemorySize, GSMEM);

    Ptrs P; float* NL1;
    cudaGetSymbolAddress((void**)&P.kvh,  g_kv_h);
    cudaGetSymbolAddress((void**)&P.kvl,  g_kv_l);
    cudaGetSymbolAddress((void**)&P.KV,   g_KV);
    cudaGetSymbolAddress((void**)&P.Qb,   g_Q);
    cudaGetSymbolAddress((void**)&P.aoh,  g_ao_h);
    cudaGetSymbolAddress((void**)&P.aol,  g_ao_l);
    cudaGetSymbolAddress((void**)&P.cath, g_cat_h);
    cudaGetSymbolAddress((void**)&P.catl, g_cat_l);
    cudaGetSymbolAddress((void**)&P.hh,   g_h_h);
    cudaGetSymbolAddress((void**)&P.hl,   g_h_l);
    cudaGetSymbolAddress((void**)&NL1,    g_NL1);
    cudaGetSymbolAddress((void**)&P.inv,  g_inv);
    cudaGetSymbolAddress((void**)&P.cq,   g_cq);
    cudaGetSymbolAddress((void**)&P.bkv,  g_bkv);
    cudaGetSymbolAddress((void**)&P.wkv,  g_wkv);
    cudaGetSymbolAddress((void**)&P.wq,   g_wq);
    cudaGetSymbolAddress((void**)&P.wo,   g_wo);
    cudaGetSymbolAddress((void**)&P.w1,   g_w1);
    cudaGetSymbolAddress((void**)&P.w2,   g_w2);

    // launch 1: all weight prep (fp16 convert + KV stack + bkv)
    prep_weights<<<(787456 + 255)/256, 256>>>(Wq, Wo, W1, W2, Wk, Wv, bk, bv,
                                              P.wq, P.wo, P.w1, P.w2, P.wkv, P.bkv);
    // launch 2
    const_q_kernel<<<2, 256>>>(Wq, bq, time_b, P.cq);

    // launch 3: stage-1 src feats; then run_layer => launches 4..9
    gather_emb_kernel<<<M_HOP2, 128>>>(node_feat, memory, neighbors1, P.cath, P.catl, M_HOP2);
    run_layer(P, 0, M_HOP2, neighbors2, nullptr, edge_idx2, edge_times2,
              timestamps, N_K, node_feat, memory, edge_feat, time_w, time_b,
              bo, b1, b2, NL1, nullptr, nullptr, 0);

    // stage 2: layer-1 embedding of src nodes (p0); SL1 -> cat col 256
    gather_emb_kernel<<<N_B, 128>>>(node_feat, memory, src_nodes, P.cath, P.catl, N_B);
    run_layer(P, 0, N_B, neighbors1, nullptr, edge_idx1, edge_times1,
              timestamps, 1, node_feat, memory, edge_feat, time_w, time_b,
              bo, b1, b2, nullptr, P.cath + 256, P.catl + 256, 384);

    // stage 3: layer-2 aggregation (p1), neighbor feats = NL1
    run_layer(P, 1, N_B, neighbors1, NL1, edge_idx1, edge_times1,
              timestamps, 1, node_feat, memory, edge_feat, time_w, time_b,
              bo, b1, b2, (float*)d_out, nullptr, nullptr, 0);
}

// round 5
// speedup vs baseline: 9.7155x; 2.1493x over previous
#include <cuda_runtime.h>
#include <cuda_fp16.h>
#include <math.h>
#include <stdint.h>

#define N_B   8192
#define N_K   10
#define N_D   128
#define N_QD  256
#define N_KD  384
#define M_HOP2 (N_B * N_K)          // 81920
#define P_HOP2 (M_HOP2 * N_K)       // 819200

// ---------------- scratch (static __device__ globals; no allocs) ------------
__device__ __half g_kv_h [(size_t)P_HOP2 * N_KD];
__device__ __half g_kv_l [(size_t)P_HOP2 * N_KD];
__device__ float  g_Q    [(size_t)M_HOP2 * N_QD];
__device__ __half g_q_h  [(size_t)M_HOP2 * N_QD];
__device__ __half g_q_l  [(size_t)M_HOP2 * N_QD];
__device__ float  g_QW   [(size_t)M_HOP2 * 768];     // q projected through Wk (2 heads x 384)
__device__ __half g_ctx_h[(size_t)M_HOP2 * 768];     // attn-weighted keyv (2 heads x 384)
__device__ __half g_ctx_l[(size_t)M_HOP2 * 768];
__device__ __half g_ao_h [(size_t)M_HOP2 * N_QD];
__device__ __half g_ao_l [(size_t)M_HOP2 * N_QD];
__device__ __half g_cat_h[(size_t)M_HOP2 * N_KD];    // [Wo-out || src] fp16-hi
__device__ __half g_cat_l[(size_t)M_HOP2 * N_KD];
__device__ __half g_h_h  [(size_t)M_HOP2 * N_D];
__device__ __half g_h_l  [(size_t)M_HOP2 * N_D];
__device__ float  g_NL1  [(size_t)M_HOP2 * N_D];
__device__ int    g_inv  [M_HOP2];
__device__ float  g_cq   [2 * N_QD];
// fp16 weights
__device__ __half g_wq [2*256*256];
__device__ __half g_wo [2*256*256];
__device__ __half g_w1 [2*128*384];
__device__ __half g_w2 [2*128*128];
__device__ __half g_wv [2*256*384];                  // Wv as-is
__device__ __half g_wqk[2*2*384*128];                // Wk head-subblocks transposed

// ---------------- helpers ---------------------------------------------------
__device__ __forceinline__ void split2h(float v, __half& h, __half& l) {
    h = __float2half_rn(v);
    l = __float2half_rn(v - __half2float(h));
}

// ---------------- merged weight prep (1 launch) -----------------------------
__global__ void prep_weights(const float* __restrict__ Wq, const float* __restrict__ Wo,
                             const float* __restrict__ W1, const float* __restrict__ W2,
                             const float* __restrict__ Wk, const float* __restrict__ Wv,
                             __half* __restrict__ wq, __half* __restrict__ wo,
                             __half* __restrict__ w1, __half* __restrict__ w2,
                             __half* __restrict__ wv, __half* __restrict__ wqk)
{
    int i = blockIdx.x * blockDim.x + threadIdx.x;
    if (i < 131072) { wq[i] = __float2half_rn(Wq[i]); return; }
    i -= 131072;
    if (i < 131072) { wo[i] = __float2half_rn(Wo[i]); return; }
    i -= 131072;
    if (i < 98304)  { w1[i] = __float2half_rn(W1[i]); return; }
    i -= 98304;
    if (i < 32768)  { w2[i] = __float2half_rn(W2[i]); return; }
    i -= 32768;
    if (i < 196608) { wv[i] = __float2half_rn(Wv[i]); return; }
    i -= 196608;
    if (i < 196608) {
        int ph = i / 49152, r = i % 49152;
        int j = r >> 7, d = r & 127;
        int p = ph >> 1, h = ph & 1;
        wqk[i] = __float2half_rn(Wk[(size_t)p*256*384 + (size_t)(h*128 + d)*384 + j]);
    }
}

// cq[j] = bq[j] + sum_t cos(tb[t]) * Wq[j,128+t]   (fp32, exact path)
__global__ void const_q_kernel(const float* __restrict__ Wq,
                               const float* __restrict__ bq,
                               const float* __restrict__ tb,
                               float* __restrict__ cq)
{
    __shared__ float ct[128];
    int p = blockIdx.x, j = threadIdx.x;
    if (j < 128) ct[j] = cosf(tb[j]);
    __syncthreads();
    const float* W = Wq + (size_t)p * N_QD * N_QD;
    float s = bq[p * N_QD + j];
    #pragma unroll 4
    for (int t = 0; t < 128; t++) s = fmaf(ct[t], W[(size_t)j * N_QD + 128 + t], s);
    cq[p * N_QD + j] = s;
}

// gather emb0 into cat buffer at col 256 (ld = 384)
__global__ void gather_emb_kernel(const float* __restrict__ nf,
                                  const float* __restrict__ mem,
                                  const int* __restrict__ idx,
                                  __half* __restrict__ dh, __half* __restrict__ dl, int n)
{
    int r = blockIdx.x;
    if (r >= n) return;
    int t = threadIdx.x;
    size_t s = (size_t)idx[r] * N_D + t;
    float v = nf[s] + mem[s];
    size_t o = (size_t)r * N_KD + 256 + t;
    split2h(v, dh[o], dl[o]);
}

// keyv builder: [emb || edge_feat || cos(dt*w+b)] -> fp16 hi/lo
__global__ void build_keyv_kernel(const int* __restrict__ neigh,
                                  const int* __restrict__ eidx,
                                  const float* __restrict__ etime,
                                  const float* __restrict__ ts, int ts_div,
                                  const float* __restrict__ nf,
                                  const float* __restrict__ mem,
                                  const float* __restrict__ ef,
                                  const float* __restrict__ dense_neigh,
                                  const float* __restrict__ tw,
                                  const float* __restrict__ tb,
                                  __half* __restrict__ kh, __half* __restrict__ kl,
                                  int Mrows)
{
    int r = blockIdx.x;
    if (r >= Mrows) return;
    int t = threadIdx.x;       // 128
    float v0;
    if (dense_neigh) v0 = dense_neigh[(size_t)r * N_D + t];
    else { size_t s = (size_t)neigh[r] * N_D + t; v0 = nf[s] + mem[s]; }
    float v1 = ef[(size_t)eidx[r] * N_D + t];
    int m = r / N_K;
    float dd = ts[m / ts_div] - etime[r];
    float v2 = cosf(__fadd_rn(__fmul_rn(dd, tw[t]), tb[t]));
    size_t o = (size_t)r * N_KD;
    split2h(v0, kh[o + t],       kl[o + t]);
    split2h(v1, kh[o + 128 + t], kl[o + 128 + t]);
    split2h(v2, kh[o + 256 + t], kl[o + 256 + t]);
}

// ---------------- fp16 2-pass tensor-core GEMM ------------------------------
#define GF_RELU 1
#define SMS  40
#define MATB (128 * SMS * 2)
#define STGB (3 * MATB)
#define NSTG 3
#define GSMEM (NSTG * STGB)

__device__ __forceinline__ void cpa16(uint32_t s, const void* g) {
    asm volatile("cp.async.cg.shared.global [%0], [%1], 16;\n" :: "r"(s), "l"(g));
}
__device__ __forceinline__ void ldm4(uint32_t* r, uint32_t a) {
    asm volatile("ldmatrix.sync.aligned.m8n8.x4.shared.b16 {%0,%1,%2,%3},[%4];\n"
                 : "=r"(r[0]), "=r"(r[1]), "=r"(r[2]), "=r"(r[3]) : "r"(a));
}
__device__ __forceinline__ void mmaf16(float* d, const uint32_t* a, uint32_t b0, uint32_t b1) {
    asm volatile("mma.sync.aligned.m16n8k16.row.col.f32.f16.f16.f32 "
                 "{%0,%1,%2,%3},{%4,%5,%6,%7},{%8,%9},{%0,%1,%2,%3};\n"
                 : "+f"(d[0]), "+f"(d[1]), "+f"(d[2]), "+f"(d[3])
                 : "r"(a[0]), "r"(a[1]), "r"(a[2]), "r"(a[3]), "r"(b0), "r"(b1));
}

__device__ __forceinline__ void issue_chunk(uint32_t sw, uint32_t bufofs,
    const __half* Ah, const __half* Al, size_t ga,
    const __half* Wh, size_t gw)
{
    uint32_t s0 = sw + bufofs;
    cpa16(s0,          Ah + ga); cpa16(s0 + 32,          Ah + ga + 16);
    cpa16(s0 + MATB,   Al + ga); cpa16(s0 + MATB + 32,   Al + ga + 16);
    cpa16(s0 + 2*MATB, Wh + gw); cpa16(s0 + 2*MATB + 32, Wh + gw + 16);
    asm volatile("cp.async.commit_group;\n");
}

__global__ __launch_bounds__(256, 2) void mma_gemm(
    const __half* __restrict__ Ah, const __half* __restrict__ Al, int lda,
    const __half* __restrict__ Wh, int ldw,
    int Kd,
    const float* __restrict__ bias,
    float* __restrict__ Cf, int ldcf,
    __half* __restrict__ Oh, __half* __restrict__ Ol, int ldo,
    const int* __restrict__ zmask, int flags)
{
    extern __shared__ __align__(16) char smem_raw[];
    uint32_t sb = (uint32_t)__cvta_generic_to_shared(smem_raw);
    int tid = threadIdx.x;
    int m0 = blockIdx.y * 128, n0 = blockIdx.x * 128;
    int lane = tid & 31, wid = tid >> 5;
    int wm = wid & 1, wn = wid >> 1;

    float d[4][4][4];
    #pragma unroll
    for (int i = 0; i < 4; i++)
        #pragma unroll
        for (int j = 0; j < 4; j++)
            #pragma unroll
            for (int r = 0; r < 4; r++) d[i][j][r] = 0.f;

    int row = tid >> 1;
    int ce  = (tid & 1) << 3;
    size_t ga0 = (size_t)(m0 + row) * lda + ce;
    size_t gw0 = (size_t)(n0 + row) * ldw + ce;
    uint32_t sw = sb + (uint32_t)(row * SMS + ce) * 2;

    int nch = Kd >> 5;
    issue_chunk(sw, 0, Ah, Al, ga0, Wh, gw0);
    if (nch > 1) issue_chunk(sw, STGB, Ah, Al, ga0 + 32, Wh, gw0 + 32);

    for (int c = 0; c < nch; c++) {
        if (c + 2 < nch) {
            int k0 = (c + 2) << 5;
            issue_chunk(sw, (uint32_t)((c + 2) % NSTG) * STGB, Ah, Al, ga0 + k0, Wh, gw0 + k0);
        }
        int issuedJ = (c + 2 < nch) ? c + 2 : nch - 1;
        int allow = issuedJ - c;
        if (allow >= 2)      asm volatile("cp.async.wait_group 2;\n" ::: "memory");
        else if (allow == 1) asm volatile("cp.async.wait_group 1;\n" ::: "memory");
        else                 asm volatile("cp.async.wait_group 0;\n" ::: "memory");
        __syncthreads();

        uint32_t base = sb + (uint32_t)(c % NSTG) * STGB;
        #pragma unroll
        for (int h = 0; h < 2; h++) {
            uint32_t ah[4][4], al[4][4], bh[2][4];
            int colA = (h << 4) + ((lane >> 4) << 3);
            #pragma unroll
            for (int mi = 0; mi < 4; mi++) {
                int r_ = wm * 64 + mi * 16 + (lane & 15);
                uint32_t ad = base + (uint32_t)(r_ * SMS + colA) * 2;
                ldm4(ah[mi], ad);
                ldm4(al[mi], ad + MATB);
            }
            #pragma unroll
            for (int nj2 = 0; nj2 < 2; nj2++) {
                int r_ = wn * 32 + nj2 * 16 + (lane & 7) + (((lane >> 3) & 1) << 3);
                uint32_t bd = base + 2 * MATB + (uint32_t)(r_ * SMS + colA) * 2;
                ldm4(bh[nj2], bd);
            }
            #pragma unroll
            for (int mi = 0; mi < 4; mi++)
                #pragma unroll
                for (int nj = 0; nj < 4; nj++)
                    mmaf16(d[mi][nj], ah[mi], bh[nj >> 1][nj & 1], bh[nj >> 1][(nj & 1) + 2]);
            #pragma unroll
            for (int mi = 0; mi < 4; mi++)
                #pragma unroll
                for (int nj = 0; nj < 4; nj++)
                    mmaf16(d[mi][nj], al[mi], bh[nj >> 1][nj & 1], bh[nj >> 1][(nj & 1) + 2]);
        }
        __syncthreads();
    }

    int gr = lane >> 2, tg = lane & 3;
    #pragma unroll
    for (int mi = 0; mi < 4; mi++) {
        int mb = m0 + wm * 64 + mi * 16 + gr;
        #pragma unroll
        for (int half = 0; half < 2; half++) {
            int m = mb + half * 8;
            bool zero = (zmask != nullptr) && (zmask[m] != 0);
            #pragma unroll
            for (int nj = 0; nj < 4; nj++) {
                int n = n0 + wn * 32 + nj * 8 + tg * 2;
                float v0 = d[mi][nj][half * 2 + 0];
                float v1 = d[mi][nj][half * 2 + 1];
                if (bias) { v0 += bias[n]; v1 += bias[n + 1]; }
                if (flags & GF_RELU) { v0 = fmaxf(v0, 0.f); v1 = fmaxf(v1, 0.f); }
                if (zero) { v0 = 0.f; v1 = 0.f; }
                if (Cf) *(float2*)&Cf[(size_t)m * ldcf + n] = make_float2(v0, v1);
                if (Oh) {
                    __half2 hh, ll;
                    split2h(v0, hh.x, ll.x);
                    split2h(v1, hh.y, ll.y);
                    *(__half2*)&Oh[(size_t)m * ldo + n] = hh;
                    *(__half2*)&Ol[(size_t)m * ldo + n] = ll;
                }
            }
        }
    }
}

// ---------------- fused attention: one warp per row m, both heads -----------
// scores = (qw . keyv + q.bk_h)/sqrt(128); softmax; ctx = sum_k attn*keyv
__global__ void attn_kernel(const float* __restrict__ Q,
                            const float* __restrict__ QW,
                            const __half* __restrict__ kh,
                            const __half* __restrict__ kl,
                            const int* __restrict__ neigh,
                            const float* __restrict__ bkp,   // bk + p*256
                            __half* __restrict__ ctxh, __half* __restrict__ ctxl,
                            int* __restrict__ inv, int M)
{
    int m = (int)((blockIdx.x * (size_t)blockDim.x + threadIdx.x) >> 5);
    int lane = threadIdx.x & 31;
    if (m >= M) return;
    const float SC = 0.08838834764831843f;   // 1/sqrt(128)

    // qb_h = q[m, h*128:...] . bk_h   (bias term of scores)
    float qb0, qb1;
    {
        const float* qp = Q + (size_t)m * N_QD;
        float4 q0 = *(const float4*)&qp[lane * 4];
        float4 q1 = *(const float4*)&qp[128 + lane * 4];
        float4 b0 = *(const float4*)&bkp[lane * 4];
        float4 b1 = *(const float4*)&bkp[128 + lane * 4];
        qb0 = q0.x*b0.x + q0.y*b0.y + q0.z*b0.z + q0.w*b0.w;
        qb1 = q1.x*b1.x + q1.y*b1.y + q1.z*b1.z + q1.w*b1.w;
        #pragma unroll
        for (int o = 16; o; o >>= 1) {
            qb0 += __shfl_xor_sync(0xffffffffu, qb0, o);
            qb1 += __shfl_xor_sync(0xffffffffu, qb1, o);
        }
    }

    float2 qw0[6], qw1[6];
    {
        const float* qwp = QW + (size_t)m * 768;
        #pragma unroll
        for (int t = 0; t < 6; t++) {
            qw0[t] = *(const float2*)&qwp[2 * lane + 64 * t];
            qw1[t] = *(const float2*)&qwp[384 + 2 * lane + 64 * t];
        }
    }

    bool msk[N_K]; bool allm = true;
    #pragma unroll
    for (int k = 0; k < N_K; k++) {
        msk[k] = (neigh[m * N_K + k] == 0);
        allm = allm && msk[k];
    }

    float s0[N_K], s1[N_K];
    #pragma unroll
    for (int k = 0; k < N_K; k++) {
        size_t rb = ((size_t)m * N_K + k) * N_KD + 2 * lane;
        float p0 = 0.f, p1 = 0.f;
        #pragma unroll
        for (int t = 0; t < 6; t++) {
            float2 af = __half22float2(*(const __half2*)&kh[rb + 64 * t]);
            float2 bf = __half22float2(*(const __half2*)&kl[rb + 64 * t]);
            float vx = af.x + bf.x, vy = af.y + bf.y;
            p0 += qw0[t].x * vx + qw0[t].y * vy;
            p1 += qw1[t].x * vx + qw1[t].y * vy;
        }
        #pragma unroll
        for (int o = 16; o; o >>= 1) {
            p0 += __shfl_xor_sync(0xffffffffu, p0, o);
            p1 += __shfl_xor_sync(0xffffffffu, p1, o);
        }
        bool mk = msk[k] && !(allm && k == 0);
        s0[k] = mk ? -1e9f : (p0 + qb0) * SC;
        s1[k] = mk ? -1e9f : (p1 + qb1) * SC;
    }

    float mx0 = s0[0], mx1 = s1[0];
    #pragma unroll
    for (int k = 1; k < N_K; k++) { mx0 = fmaxf(mx0, s0[k]); mx1 = fmaxf(mx1, s1[k]); }
    float sm0 = 0.f, sm1 = 0.f;
    #pragma unroll
    for (int k = 0; k < N_K; k++) {
        s0[k] = expf(s0[k] - mx0); sm0 += s0[k];
        s1[k] = expf(s1[k] - mx1); sm1 += s1[k];
    }
    float r0 = 1.f / sm0, r1 = 1.f / sm1;

    float2 a0[6], a1[6];
    #pragma unroll
    for (int t = 0; t < 6; t++) { a0[t] = make_float2(0.f, 0.f); a1[t] = make_float2(0.f, 0.f); }
    #pragma unroll
    for (int k = 0; k < N_K; k++) {
        float w0 = s0[k] * r0, w1 = s1[k] * r1;
        size_t rb = ((size_t)m * N_K + k) * N_KD + 2 * lane;
        #pragma unroll
        for (int t = 0; t < 6; t++) {
            float2 af = __half22float2(*(const __half2*)&kh[rb + 64 * t]);
            float2 bf = __half22float2(*(const __half2*)&kl[rb + 64 * t]);
            float vx = af.x + bf.x, vy = af.y + bf.y;
            a0[t].x = fmaf(w0, vx, a0[t].x); a0[t].y = fmaf(w0, vy, a0[t].y);
            a1[t].x = fmaf(w1, vx, a1[t].x); a1[t].y = fmaf(w1, vy, a1[t].y);
        }
    }

    size_t ob = (size_t)m * 768 + 2 * lane;
    #pragma unroll
    for (int t = 0; t < 6; t++) {
        __half2 hh, ll;
        split2h(a0[t].x, hh.x, ll.x); split2h(a0[t].y, hh.y, ll.y);
        *(__half2*)&ctxh[ob + 64 * t] = hh;
        *(__half2*)&ctxl[ob + 64 * t] = ll;
        split2h(a1[t].x, hh.x, ll.x); split2h(a1[t].y, hh.y, ll.y);
        *(__half2*)&ctxh[ob + 384 + 64 * t] = hh;
        *(__half2*)&ctxl[ob + 384 + 64 * t] = ll;
    }
    if (lane == 0) inv[m] = allm ? 1 : 0;
}

// ---------------- one temporal attention layer ------------------------------
struct Ptrs {
    __half *kvh, *kvl, *qh, *ql, *ctxh, *ctxl, *aoh, *aol, *cath, *catl, *hh, *hl;
    float *Qb, *QW; int* inv;
    __half *wq, *wo, *w1, *w2, *wv, *wqk;
    float *cq;
};

static void run_layer(const Ptrs& P, int p, int M,
                      const int* neigh, const float* dense_neigh,
                      const int* eidx, const float* etime,
                      const float* ts, int ts_div,
                      const float* nf, const float* mem, const float* ef,
                      const float* tw, const float* tb,
                      const float* bk, const float* bv,
                      const float* bo, const float* b1, const float* b2,
                      float* outCf, __half* outOh, __half* outOl, int out_ldo)
{
    int MK = M * N_K;
    build_keyv_kernel<<<MK, 128>>>(neigh, eidx, etime, ts, ts_div, nf, mem, ef,
                                   dense_neigh, tw, tb, P.kvh, P.kvl, MK);
    // Q = src @ Wq[:,:128]^T + cq   -> fp32 + fp16 hi/lo
    mma_gemm<<<dim3(2, M/128), 256, GSMEM>>>(
        P.cath + 256, P.catl + 256, 384,
        P.wq + (size_t)p*65536, 256, 128,
        P.cq + p*256, P.Qb, 256, P.qh, P.ql, 256, nullptr, 0);
    // qw_h = q_h @ WkT_h   (per head, N=384, Kd=128) -> fp32
    for (int h = 0; h < 2; h++)
        mma_gemm<<<dim3(3, M/128), 256, GSMEM>>>(
            P.qh + h*128, P.ql + h*128, 256,
            P.wqk + (size_t)(p*2 + h)*49152, 128, 128,
            nullptr, P.QW + h*384, 768, nullptr, nullptr, 0, nullptr, 0);
    attn_kernel<<<(M*32 + 255)/256, 256>>>(P.Qb, P.QW, P.kvh, P.kvl, neigh,
                                           bk + p*256, P.ctxh, P.ctxl, P.inv, M);
    // ao_h = ctx_h @ Wv_h^T + bv_h   (per head, N=128, Kd=384)
    for (int h = 0; h < 2; h++)
        mma_gemm<<<dim3(1, M/128), 256, GSMEM>>>(
            P.ctxh + h*384, P.ctxl + h*384, 768,
            P.wv + (size_t)(p*256 + h*128)*384, 384, 384,
            bv + p*256 + h*128, nullptr, 0, P.aoh + h*128, P.aol + h*128, 256, nullptr, 0);
    // Wo projection -> cat cols 0..255 (zeroed on invalid rows)
    mma_gemm<<<dim3(2, M/128), 256, GSMEM>>>(
        P.aoh, P.aol, 256,
        P.wo + (size_t)p*65536, 256, 256,
        bo + p*256, nullptr, 0, P.cath, P.catl, 384, P.inv, 0);
    // h = relu(cat @ W1^T + b1)
    mma_gemm<<<dim3(1, M/128), 256, GSMEM>>>(
        P.cath, P.catl, 384,
        P.w1 + (size_t)p*49152, 384, 384,
        b1 + p*128, nullptr, 0, P.hh, P.hl, 128, nullptr, GF_RELU);
    // out = h @ W2^T + b2
    mma_gemm<<<dim3(1, M/128), 256, GSMEM>>>(
        P.hh, P.hl, 128,
        P.w2 + (size_t)p*16384, 128, 128,
        b2 + p*128, outCf, 128, outOh, outOl, out_ldo, nullptr, 0);
}

// ---------------- entry -----------------------------------------------------
extern "C" void kernel_launch(void* const* d_in, const int* in_sizes, int n_in,
                              void* d_out, int out_size)
{
    const float* node_feat   = (const float*)d_in[0];
    const float* memory      = (const float*)d_in[1];
    const float* edge_feat   = (const float*)d_in[2];
    const float* time_w      = (const float*)d_in[3];
    const float* time_b      = (const float*)d_in[4];
    const float* Wq          = (const float*)d_in[5];
    const float* bq          = (const float*)d_in[6];
    const float* Wk          = (const float*)d_in[7];
    const float* bk          = (const float*)d_in[8];
    const float* Wv          = (const float*)d_in[9];
    const float* bv          = (const float*)d_in[10];
    const float* Wo          = (const float*)d_in[11];
    const float* bo          = (const float*)d_in[12];
    const float* W1          = (const float*)d_in[13];
    const float* b1          = (const float*)d_in[14];
    const float* W2          = (const float*)d_in[15];
    const float* b2          = (const float*)d_in[16];
    const float* timestamps  = (const float*)d_in[17];
    const int*   src_nodes   = (const int*)d_in[18];
    const int*   neighbors1  = (const int*)d_in[19];
    const int*   edge_idx1   = (const int*)d_in[20];
    const float* edge_times1 = (const float*)d_in[21];
    const int*   neighbors2  = (const int*)d_in[22];
    const int*   edge_idx2   = (const int*)d_in[23];
    const float* edge_times2 = (const float*)d_in[24];

    cudaFuncSetAttribute(mma_gemm, cudaFuncAttributeMaxDynamicSharedMemorySize, GSMEM);

    Ptrs P; float* NL1;
    cudaGetSymbolAddress((void**)&P.kvh,  g_kv_h);
    cudaGetSymbolAddress((void**)&P.kvl,  g_kv_l);
    cudaGetSymbolAddress((void**)&P.Qb,   g_Q);
    cudaGetSymbolAddress((void**)&P.qh,   g_q_h);
    cudaGetSymbolAddress((void**)&P.ql,   g_q_l);
    cudaGetSymbolAddress((void**)&P.QW,   g_QW);
    cudaGetSymbolAddress((void**)&P.ctxh, g_ctx_h);
    cudaGetSymbolAddress((void**)&P.ctxl, g_ctx_l);
    cudaGetSymbolAddress((void**)&P.aoh,  g_ao_h);
    cudaGetSymbolAddress((void**)&P.aol,  g_ao_l);
    cudaGetSymbolAddress((void**)&P.cath, g_cat_h);
    cudaGetSymbolAddress((void**)&P.catl, g_cat_l);
    cudaGetSymbolAddress((void**)&P.hh,   g_h_h);
    cudaGetSymbolAddress((void**)&P.hl,   g_h_l);
    cudaGetSymbolAddress((void**)&NL1,    g_NL1);
    cudaGetSymbolAddress((void**)&P.inv,  g_inv);
    cudaGetSymbolAddress((void**)&P.cq,   g_cq);
    cudaGetSymbolAddress((void**)&P.wq,   g_wq);
    cudaGetSymbolAddress((void**)&P.wo,   g_wo);
    cudaGetSymbolAddress((void**)&P.w1,   g_w1);
    cudaGetSymbolAddress((void**)&P.w2,   g_w2);
    cudaGetSymbolAddress((void**)&P.wv,   g_wv);
    cudaGetSymbolAddress((void**)&P.wqk,  g_wqk);

    prep_weights<<<3072, 256>>>(Wq, Wo, W1, W2, Wk, Wv,
                                P.wq, P.wo, P.w1, P.w2, P.wv, P.wqk);
    const_q_kernel<<<2, 256>>>(Wq, bq, time_b, P.cq);

    // stage 1: layer-1 embedding of flattened first-hop neighbors (p0)
    gather_emb_kernel<<<M_HOP2, 128>>>(node_feat, memory, neighbors1, P.cath, P.catl, M_HOP2);
    run_layer(P, 0, M_HOP2, neighbors2, nullptr, edge_idx2, edge_times2,
              timestamps, N_K, node_feat, memory, edge_feat, time_w, time_b,
              bk, bv, bo, b1, b2, NL1, nullptr, nullptr, 0);

    // stage 2: layer-1 embedding of src nodes (p0); SL1 -> cat col 256
    gather_emb_kernel<<<N_B, 128>>>(node_feat, memory, src_nodes, P.cath, P.catl, N_B);
    run_layer(P, 0, N_B, neighbors1, nullptr, edge_idx1, edge_times1,
              timestamps, 1, node_feat, memory, edge_feat, time_w, time_b,
              bk, bv, bo, b1, b2, nullptr, P.cath + 256, P.catl + 256, 384);

    // stage 3: layer-2 aggregation (p1), neighbor feats = NL1
    run_layer(P, 1, N_B, neighbors1, NL1, edge_idx1, edge_times1,
              timestamps, 1, node_feat, memory, edge_feat, time_w, time_b,
              bk, bv, bo, b1, b2, (float*)d_out, nullptr, nullptr, 0);
}

// round 6
// speedup vs baseline: 12.4410x; 1.2805x over previous
#include <cuda_runtime.h>
#include <cuda_fp16.h>
#include <math.h>
#include <stdint.h>

#define N_B   8192
#define N_K   10
#define N_D   128
#define N_QD  256
#define N_KD  384
#define M_HOP2 (N_B * N_K)          // 81920

// ---------------- scratch (static __device__ globals; no allocs) ------------
__device__ float  g_Q    [(size_t)M_HOP2 * N_QD];
__device__ __half g_q_h  [(size_t)M_HOP2 * N_QD];
__device__ __half g_q_l  [(size_t)M_HOP2 * N_QD];
__device__ float  g_QW   [(size_t)M_HOP2 * 768];     // q projected through Wk (2 heads x 384)
__device__ __half g_ctx_h[(size_t)M_HOP2 * 768];     // attn-weighted keyv (2 heads x 384)
__device__ __half g_ctx_l[(size_t)M_HOP2 * 768];
__device__ __half g_ao_h [(size_t)M_HOP2 * N_QD];
__device__ __half g_ao_l [(size_t)M_HOP2 * N_QD];
__device__ __half g_cat_h[(size_t)M_HOP2 * N_KD];    // [Wo-out || src] fp16-hi
__device__ __half g_cat_l[(size_t)M_HOP2 * N_KD];
__device__ __half g_h_h  [(size_t)M_HOP2 * N_D];
__device__ __half g_h_l  [(size_t)M_HOP2 * N_D];
__device__ float  g_NL1  [(size_t)M_HOP2 * N_D];
__device__ int    g_inv  [M_HOP2];
__device__ float  g_cq   [2 * N_QD];
// fp16 weights
__device__ __half g_wq [2*256*256];
__device__ __half g_wo [2*256*256];
__device__ __half g_w1 [2*128*384];
__device__ __half g_w2 [2*128*128];
__device__ __half g_wv [2*256*384];                  // Wv as-is
__device__ __half g_wqk[2*2*384*128];                // Wk head-subblocks transposed

// ---------------- helpers ---------------------------------------------------
__device__ __forceinline__ void split2h(float v, __half& h, __half& l) {
    h = __float2half_rn(v);
    l = __float2half_rn(v - __half2float(h));
}

// ---------------- merged weight prep (1 launch) -----------------------------
__global__ void prep_weights(const float* __restrict__ Wq, const float* __restrict__ Wo,
                             const float* __restrict__ W1, const float* __restrict__ W2,
                             const float* __restrict__ Wk, const float* __restrict__ Wv,
                             __half* __restrict__ wq, __half* __restrict__ wo,
                             __half* __restrict__ w1, __half* __restrict__ w2,
                             __half* __restrict__ wv, __half* __restrict__ wqk)
{
    int i = blockIdx.x * blockDim.x + threadIdx.x;
    if (i < 131072) { wq[i] = __float2half_rn(Wq[i]); return; }
    i -= 131072;
    if (i < 131072) { wo[i] = __float2half_rn(Wo[i]); return; }
    i -= 131072;
    if (i < 98304)  { w1[i] = __float2half_rn(W1[i]); return; }
    i -= 98304;
    if (i < 32768)  { w2[i] = __float2half_rn(W2[i]); return; }
    i -= 32768;
    if (i < 196608) { wv[i] = __float2half_rn(Wv[i]); return; }
    i -= 196608;
    if (i < 196608) {
        int ph = i / 49152, r = i % 49152;
        int j = r >> 7, d = r & 127;
        int p = ph >> 1, h = ph & 1;
        wqk[i] = __float2half_rn(Wk[(size_t)p*256*384 + (size_t)(h*128 + d)*384 + j]);
    }
}

// cq[j] = bq[j] + sum_t cos(tb[t]) * Wq[j,128+t]   (fp32, exact path)
__global__ void const_q_kernel(const float* __restrict__ Wq,
                               const float* __restrict__ bq,
                               const float* __restrict__ tb,
                               float* __restrict__ cq)
{
    __shared__ float ct[128];
    int p = blockIdx.x, j = threadIdx.x;
    if (j < 128) ct[j] = cosf(tb[j]);
    __syncthreads();
    const float* W = Wq + (size_t)p * N_QD * N_QD;
    float s = bq[p * N_QD + j];
    #pragma unroll 4
    for (int t = 0; t < 128; t++) s = fmaf(ct[t], W[(size_t)j * N_QD + 128 + t], s);
    cq[p * N_QD + j] = s;
}

// gather emb0 into cat buffer at col 256 (ld = 384)
__global__ void gather_emb_kernel(const float* __restrict__ nf,
                                  const float* __restrict__ mem,
                                  const int* __restrict__ idx,
                                  __half* __restrict__ dh, __half* __restrict__ dl, int n)
{
    int r = blockIdx.x;
    if (r >= n) return;
    int t = threadIdx.x;
    size_t s = (size_t)idx[r] * N_D + t;
    float v = nf[s] + mem[s];
    size_t o = (size_t)r * N_KD + 256 + t;
    split2h(v, dh[o], dl[o]);
}

// ---------------- fp16 2-pass tensor-core GEMM ------------------------------
#define GF_RELU 1
#define SMS  40
#define MATB (128 * SMS * 2)
#define STGB (3 * MATB)
#define NSTG 3
#define GSMEM (NSTG * STGB)

__device__ __forceinline__ void cpa16(uint32_t s, const void* g) {
    asm volatile("cp.async.cg.shared.global [%0], [%1], 16;\n" :: "r"(s), "l"(g));
}
__device__ __forceinline__ void ldm4(uint32_t* r, uint32_t a) {
    asm volatile("ldmatrix.sync.aligned.m8n8.x4.shared.b16 {%0,%1,%2,%3},[%4];\n"
                 : "=r"(r[0]), "=r"(r[1]), "=r"(r[2]), "=r"(r[3]) : "r"(a));
}
__device__ __forceinline__ void mmaf16(float* d, const uint32_t* a, uint32_t b0, uint32_t b1) {
    asm volatile("mma.sync.aligned.m16n8k16.row.col.f32.f16.f16.f32 "
                 "{%0,%1,%2,%3},{%4,%5,%6,%7},{%8,%9},{%0,%1,%2,%3};\n"
                 : "+f"(d[0]), "+f"(d[1]), "+f"(d[2]), "+f"(d[3])
                 : "r"(a[0]), "r"(a[1]), "r"(a[2]), "r"(a[3]), "r"(b0), "r"(b1));
}

__device__ __forceinline__ void issue_chunk(uint32_t sw, uint32_t bufofs,
    const __half* Ah, const __half* Al, size_t ga,
    const __half* Wh, size_t gw)
{
    uint32_t s0 = sw + bufofs;
    cpa16(s0,          Ah + ga); cpa16(s0 + 32,          Ah + ga + 16);
    cpa16(s0 + MATB,   Al + ga); cpa16(s0 + MATB + 32,   Al + ga + 16);
    cpa16(s0 + 2*MATB, Wh + gw); cpa16(s0 + 2*MATB + 32, Wh + gw + 16);
    asm volatile("cp.async.commit_group;\n");
}

__global__ __launch_bounds__(256, 2) void mma_gemm(
    const __half* __restrict__ Ah, const __half* __restrict__ Al, int lda,
    const __half* __restrict__ Wh, int ldw,
    int Kd,
    const float* __restrict__ bias,
    float* __restrict__ Cf, int ldcf,
    __half* __restrict__ Oh, __half* __restrict__ Ol, int ldo,
    const int* __restrict__ zmask, int flags)
{
    extern __shared__ __align__(16) char smem_raw[];
    uint32_t sb = (uint32_t)__cvta_generic_to_shared(smem_raw);
    int tid = threadIdx.x;
    int m0 = blockIdx.y * 128, n0 = blockIdx.x * 128;
    int lane = tid & 31, wid = tid >> 5;
    int wm = wid & 1, wn = wid >> 1;

    float d[4][4][4];
    #pragma unroll
    for (int i = 0; i < 4; i++)
        #pragma unroll
        for (int j = 0; j < 4; j++)
            #pragma unroll
            for (int r = 0; r < 4; r++) d[i][j][r] = 0.f;

    int row = tid >> 1;
    int ce  = (tid & 1) << 3;
    size_t ga0 = (size_t)(m0 + row) * lda + ce;
    size_t gw0 = (size_t)(n0 + row) * ldw + ce;
    uint32_t sw = sb + (uint32_t)(row * SMS + ce) * 2;

    int nch = Kd >> 5;
    issue_chunk(sw, 0, Ah, Al, ga0, Wh, gw0);
    if (nch > 1) issue_chunk(sw, STGB, Ah, Al, ga0 + 32, Wh, gw0 + 32);

    for (int c = 0; c < nch; c++) {
        if (c + 2 < nch) {
            int k0 = (c + 2) << 5;
            issue_chunk(sw, (uint32_t)((c + 2) % NSTG) * STGB, Ah, Al, ga0 + k0, Wh, gw0 + k0);
        }
        int issuedJ = (c + 2 < nch) ? c + 2 : nch - 1;
        int allow = issuedJ - c;
        if (allow >= 2)      asm volatile("cp.async.wait_group 2;\n" ::: "memory");
        else if (allow == 1) asm volatile("cp.async.wait_group 1;\n" ::: "memory");
        else                 asm volatile("cp.async.wait_group 0;\n" ::: "memory");
        __syncthreads();

        uint32_t base = sb + (uint32_t)(c % NSTG) * STGB;
        #pragma unroll
        for (int h = 0; h < 2; h++) {
            uint32_t ah[4][4], al[4][4], bh[2][4];
            int colA = (h << 4) + ((lane >> 4) << 3);
            #pragma unroll
            for (int mi = 0; mi < 4; mi++) {
                int r_ = wm * 64 + mi * 16 + (lane & 15);
                uint32_t ad = base + (uint32_t)(r_ * SMS + colA) * 2;
                ldm4(ah[mi], ad);
                ldm4(al[mi], ad + MATB);
            }
            #pragma unroll
            for (int nj2 = 0; nj2 < 2; nj2++) {
                int r_ = wn * 32 + nj2 * 16 + (lane & 7) + (((lane >> 3) & 1) << 3);
                uint32_t bd = base + 2 * MATB + (uint32_t)(r_ * SMS + colA) * 2;
                ldm4(bh[nj2], bd);
            }
            #pragma unroll
            for (int mi = 0; mi < 4; mi++)
                #pragma unroll
                for (int nj = 0; nj < 4; nj++)
                    mmaf16(d[mi][nj], ah[mi], bh[nj >> 1][nj & 1], bh[nj >> 1][(nj & 1) + 2]);
            #pragma unroll
            for (int mi = 0; mi < 4; mi++)
                #pragma unroll
                for (int nj = 0; nj < 4; nj++)
                    mmaf16(d[mi][nj], al[mi], bh[nj >> 1][nj & 1], bh[nj >> 1][(nj & 1) + 2]);
        }
        __syncthreads();
    }

    int gr = lane >> 2, tg = lane & 3;
    #pragma unroll
    for (int mi = 0; mi < 4; mi++) {
        int mb = m0 + wm * 64 + mi * 16 + gr;
        #pragma unroll
        for (int half = 0; half < 2; half++) {
            int m = mb + half * 8;
            bool zero = (zmask != nullptr) && (zmask[m] != 0);
            #pragma unroll
            for (int nj = 0; nj < 4; nj++) {
                int n = n0 + wn * 32 + nj * 8 + tg * 2;
                float v0 = d[mi][nj][half * 2 + 0];
                float v1 = d[mi][nj][half * 2 + 1];
                if (bias) { v0 += bias[n]; v1 += bias[n + 1]; }
                if (flags & GF_RELU) { v0 = fmaxf(v0, 0.f); v1 = fmaxf(v1, 0.f); }
                if (zero) { v0 = 0.f; v1 = 0.f; }
                if (Cf) *(float2*)&Cf[(size_t)m * ldcf + n] = make_float2(v0, v1);
                if (Oh) {
                    __half2 hh, ll;
                    split2h(v0, hh.x, ll.x);
                    split2h(v1, hh.y, ll.y);
                    *(__half2*)&Oh[(size_t)m * ldo + n] = hh;
                    *(__half2*)&Ol[(size_t)m * ldo + n] = ll;
                }
            }
        }
    }
}

// ---------------- fused keyv-build + attention ------------------------------
// One warp per row m, both heads. keyv rows built on the fly in fp32:
//   [emb(node) || edge_feat || cos(dt*w+b)]
// Pass A: scores s_h[k] = (qw_h . keyv_k + q.bk_h)/sqrt(128)  (cos cached in smem)
// Pass B: ctx_h = sum_k softmax(s_h)[k] * keyv_k  (gathers re-read; L2-hot)
__global__ __launch_bounds__(128) void fused_attn(
    const int* __restrict__ neigh,
    const int* __restrict__ eidx,
    const float* __restrict__ etime,
    const float* __restrict__ ts, int ts_div,
    const float* __restrict__ nf, const float* __restrict__ mem,
    const float* __restrict__ ef,
    const float* __restrict__ dense_neigh,
    const float* __restrict__ tw, const float* __restrict__ tb,
    const float* __restrict__ Q, const float* __restrict__ QW,
    const float* __restrict__ bkp,
    __half* __restrict__ ctxh, __half* __restrict__ ctxl,
    int* __restrict__ inv, int M)
{
    __shared__ float s_tw[128], s_tb[128];
    __shared__ float cosb[4][N_K * 128];
    int tid = threadIdx.x;
    s_tw[tid] = tw[tid];
    s_tb[tid] = tb[tid];
    __syncthreads();

    int wl = tid >> 5, lane = tid & 31;
    int m = blockIdx.x * 4 + wl;
    if (m >= M) return;
    const float SC = 0.08838834764831843f;   // 1/sqrt(128)
    float* cb = cosb[wl];

    // qb_h = q[m, h*128:...] . bk_h
    float qb0, qb1;
    {
        const float* qp = Q + (size_t)m * N_QD;
        float4 q0 = *(const float4*)&qp[lane * 4];
        float4 q1 = *(const float4*)&qp[128 + lane * 4];
        float4 b0 = *(const float4*)&bkp[lane * 4];
        float4 b1 = *(const float4*)&bkp[128 + lane * 4];
        qb0 = q0.x*b0.x + q0.y*b0.y + q0.z*b0.z + q0.w*b0.w;
        qb1 = q1.x*b1.x + q1.y*b1.y + q1.z*b1.z + q1.w*b1.w;
        #pragma unroll
        for (int o = 16; o; o >>= 1) {
            qb0 += __shfl_xor_sync(0xffffffffu, qb0, o);
            qb1 += __shfl_xor_sync(0xffffffffu, qb1, o);
        }
    }

    float2 qw0[6], qw1[6];
    {
        const float* qwp = QW + (size_t)m * 768;
        #pragma unroll
        for (int t = 0; t < 6; t++) {
            qw0[t] = *(const float2*)&qwp[2 * lane + 64 * t];
            qw1[t] = *(const float2*)&qwp[384 + 2 * lane + 64 * t];
        }
    }

    float tsv = ts[m / ts_div];
    int jj = 2 * lane;

    bool msk[N_K]; bool allm = true;
    int nd[N_K], ed[N_K];
    #pragma unroll
    for (int k = 0; k < N_K; k++) {
        nd[k] = neigh[m * N_K + k];
        ed[k] = eidx [m * N_K + k];
        msk[k] = (nd[k] == 0);
        allm = allm && msk[k];
    }

    // ---- pass A: scores
    float s0[N_K], s1[N_K];
    #pragma unroll
    for (int k = 0; k < N_K; k++) {
        float2 v[6];
        if (dense_neigh) {
            const float* dr = dense_neigh + (size_t)(m * N_K + k) * N_D;
            v[0] = *(const float2*)&dr[jj];
            v[1] = *(const float2*)&dr[jj + 64];
        } else {
            const float* nr = nf  + (size_t)nd[k] * N_D;
            const float* mr = mem + (size_t)nd[k] * N_D;
            float2 a0 = *(const float2*)&nr[jj],      b0 = *(const float2*)&mr[jj];
            float2 a1 = *(const float2*)&nr[jj + 64], b1 = *(const float2*)&mr[jj + 64];
            v[0] = make_float2(a0.x + b0.x, a0.y + b0.y);
            v[1] = make_float2(a1.x + b1.x, a1.y + b1.y);
        }
        {
            const float* er = ef + (size_t)ed[k] * N_D;
            v[2] = *(const float2*)&er[jj];
            v[3] = *(const float2*)&er[jj + 64];
        }
        float dd = tsv - etime[m * N_K + k];
        #pragma unroll
        for (int t = 4; t < 6; t++) {
            int j = jj + (t - 4) * 64;
            float cx = cosf(__fadd_rn(__fmul_rn(dd, s_tw[j]),     s_tb[j]));
            float cy = cosf(__fadd_rn(__fmul_rn(dd, s_tw[j + 1]), s_tb[j + 1]));
            v[t] = make_float2(cx, cy);
            *(float2*)&cb[k * 128 + j] = v[t];
        }
        float p0 = 0.f, p1 = 0.f;
        #pragma unroll
        for (int t = 0; t < 6; t++) {
            p0 += qw0[t].x * v[t].x + qw0[t].y * v[t].y;
            p1 += qw1[t].x * v[t].x + qw1[t].y * v[t].y;
        }
        #pragma unroll
        for (int o = 16; o; o >>= 1) {
            p0 += __shfl_xor_sync(0xffffffffu, p0, o);
            p1 += __shfl_xor_sync(0xffffffffu, p1, o);
        }
        bool mk = msk[k] && !(allm && k == 0);
        s0[k] = mk ? -1e9f : (p0 + qb0) * SC;
        s1[k] = mk ? -1e9f : (p1 + qb1) * SC;
    }

    float mx0 = s0[0], mx1 = s1[0];
    #pragma unroll
    for (int k = 1; k < N_K; k++) { mx0 = fmaxf(mx0, s0[k]); mx1 = fmaxf(mx1, s1[k]); }
    float sm0 = 0.f, sm1 = 0.f;
    #pragma unroll
    for (int k = 0; k < N_K; k++) {
        s0[k] = expf(s0[k] - mx0); sm0 += s0[k];
        s1[k] = expf(s1[k] - mx1); sm1 += s1[k];
    }
    float r0 = 1.f / sm0, r1 = 1.f / sm1;

    // ---- pass B: ctx accumulation (gathers hit L2; cos from smem)
    float2 a0[6], a1[6];
    #pragma unroll
    for (int t = 0; t < 6; t++) { a0[t] = make_float2(0.f, 0.f); a1[t] = make_float2(0.f, 0.f); }
    #pragma unroll
    for (int k = 0; k < N_K; k++) {
        float w0 = s0[k] * r0, w1 = s1[k] * r1;
        float2 v[6];
        if (dense_neigh) {
            const float* dr = dense_neigh + (size_t)(m * N_K + k) * N_D;
            v[0] = *(const float2*)&dr[jj];
            v[1] = *(const float2*)&dr[jj + 64];
        } else {
            const float* nr = nf  + (size_t)nd[k] * N_D;
            const float* mr = mem + (size_t)nd[k] * N_D;
            float2 c0 = *(const float2*)&nr[jj],      d0 = *(const float2*)&mr[jj];
            float2 c1 = *(const float2*)&nr[jj + 64], d1 = *(const float2*)&mr[jj + 64];
            v[0] = make_float2(c0.x + d0.x, c0.y + d0.y);
            v[1] = make_float2(c1.x + d1.x, c1.y + d1.y);
        }
        {
            const float* er = ef + (size_t)ed[k] * N_D;
            v[2] = *(const float2*)&er[jj];
            v[3] = *(const float2*)&er[jj + 64];
        }
        v[4] = *(const float2*)&cb[k * 128 + jj];
        v[5] = *(const float2*)&cb[k * 128 + jj + 64];
        #pragma unroll
        for (int t = 0; t < 6; t++) {
            a0[t].x = fmaf(w0, v[t].x, a0[t].x); a0[t].y = fmaf(w0, v[t].y, a0[t].y);
            a1[t].x = fmaf(w1, v[t].x, a1[t].x); a1[t].y = fmaf(w1, v[t].y, a1[t].y);
        }
    }

    size_t ob = (size_t)m * 768 + jj;
    #pragma unroll
    for (int t = 0; t < 6; t++) {
        __half2 hh, ll;
        split2h(a0[t].x, hh.x, ll.x); split2h(a0[t].y, hh.y, ll.y);
        *(__half2*)&ctxh[ob + 64 * t] = hh;
        *(__half2*)&ctxl[ob + 64 * t] = ll;
        split2h(a1[t].x, hh.x, ll.x); split2h(a1[t].y, hh.y, ll.y);
        *(__half2*)&ctxh[ob + 384 + 64 * t] = hh;
        *(__half2*)&ctxl[ob + 384 + 64 * t] = ll;
    }
    if (lane == 0) inv[m] = allm ? 1 : 0;
}

// ---------------- one temporal attention layer ------------------------------
struct Ptrs {
    __half *qh, *ql, *ctxh, *ctxl, *aoh, *aol, *cath, *catl, *hh, *hl;
    float *Qb, *QW; int* inv;
    __half *wq, *wo, *w1, *w2, *wv, *wqk;
    float *cq;
};

static void run_layer(const Ptrs& P, int p, int M,
                      const int* neigh, const float* dense_neigh,
                      const int* eidx, const float* etime,
                      const float* ts, int ts_div,
                      const float* nf, const float* mem, const float* ef,
                      const float* tw, const float* tb,
                      const float* bk, const float* bv,
                      const float* bo, const float* b1, const float* b2,
                      float* outCf, __half* outOh, __half* outOl, int out_ldo)
{
    // Q = src @ Wq[:,:128]^T + cq   -> fp32 + fp16 hi/lo
    mma_gemm<<<dim3(2, M/128), 256, GSMEM>>>(
        P.cath + 256, P.catl + 256, 384,
        P.wq + (size_t)p*65536, 256, 128,
        P.cq + p*256, P.Qb, 256, P.qh, P.ql, 256, nullptr, 0);
    // qw_h = q_h @ WkT_h   (per head, N=384, Kd=128) -> fp32
    for (int h = 0; h < 2; h++)
        mma_gemm<<<dim3(3, M/128), 256, GSMEM>>>(
            P.qh + h*128, P.ql + h*128, 256,
            P.wqk + (size_t)(p*2 + h)*49152, 128, 128,
            nullptr, P.QW + h*384, 768, nullptr, nullptr, 0, nullptr, 0);
    // fused keyv-build + attention
    fused_attn<<<(M + 3) / 4, 128>>>(neigh, eidx, etime, ts, ts_div,
                                     nf, mem, ef, dense_neigh, tw, tb,
                                     P.Qb, P.QW, bk + p*256,
                                     P.ctxh, P.ctxl, P.inv, M);
    // ao_h = ctx_h @ Wv_h^T + bv_h   (per head, N=128, Kd=384)
    for (int h = 0; h < 2; h++)
        mma_gemm<<<dim3(1, M/128), 256, GSMEM>>>(
            P.ctxh + h*384, P.ctxl + h*384, 768,
            P.wv + (size_t)(p*256 + h*128)*384, 384, 384,
            bv + p*256 + h*128, nullptr, 0, P.aoh + h*128, P.aol + h*128, 256, nullptr, 0);
    // Wo projection -> cat cols 0..255 (zeroed on invalid rows)
    mma_gemm<<<dim3(2, M/128), 256, GSMEM>>>(
        P.aoh, P.aol, 256,
        P.wo + (size_t)p*65536, 256, 256,
        bo + p*256, nullptr, 0, P.cath, P.catl, 384, P.inv, 0);
    // h = relu(cat @ W1^T + b1)
    mma_gemm<<<dim3(1, M/128), 256, GSMEM>>>(
        P.cath, P.catl, 384,
        P.w1 + (size_t)p*49152, 384, 384,
        b1 + p*128, nullptr, 0, P.hh, P.hl, 128, nullptr, GF_RELU);
    // out = h @ W2^T + b2
    mma_gemm<<<dim3(1, M/128), 256, GSMEM>>>(
        P.hh, P.hl, 128,
        P.w2 + (size_t)p*16384, 128, 128,
        b2 + p*128, outCf, 128, outOh, outOl, out_ldo, nullptr, 0);
}

// ---------------- entry -----------------------------------------------------
extern "C" void kernel_launch(void* const* d_in, const int* in_sizes, int n_in,
                              void* d_out, int out_size)
{
    const float* node_feat   = (const float*)d_in[0];
    const float* memory      = (const float*)d_in[1];
    const float* edge_feat   = (const float*)d_in[2];
    const float* time_w      = (const float*)d_in[3];
    const float* time_b      = (const float*)d_in[4];
    const float* Wq          = (const float*)d_in[5];
    const float* bq          = (const float*)d_in[6];
    const float* Wk          = (const float*)d_in[7];
    const float* bk          = (const float*)d_in[8];
    const float* Wv          = (const float*)d_in[9];
    const float* bv          = (const float*)d_in[10];
    const float* Wo          = (const float*)d_in[11];
    const float* bo          = (const float*)d_in[12];
    const float* W1          = (const float*)d_in[13];
    const float* b1          = (const float*)d_in[14];
    const float* W2          = (const float*)d_in[15];
    const float* b2          = (const float*)d_in[16];
    const float* timestamps  = (const float*)d_in[17];
    const int*   src_nodes   = (const int*)d_in[18];
    const int*   neighbors1  = (const int*)d_in[19];
    const int*   edge_idx1   = (const int*)d_in[20];
    const float* edge_times1 = (const float*)d_in[21];
    const int*   neighbors2  = (const int*)d_in[22];
    const int*   edge_idx2   = (const int*)d_in[23];
    const float* edge_times2 = (const float*)d_in[24];

    cudaFuncSetAttribute(mma_gemm, cudaFuncAttributeMaxDynamicSharedMemorySize, GSMEM);

    Ptrs P; float* NL1;
    cudaGetSymbolAddress((void**)&P.Qb,   g_Q);
    cudaGetSymbolAddress((void**)&P.qh,   g_q_h);
    cudaGetSymbolAddress((void**)&P.ql,   g_q_l);
    cudaGetSymbolAddress((void**)&P.QW,   g_QW);
    cudaGetSymbolAddress((void**)&P.ctxh, g_ctx_h);
    cudaGetSymbolAddress((void**)&P.ctxl, g_ctx_l);
    cudaGetSymbolAddress((void**)&P.aoh,  g_ao_h);
    cudaGetSymbolAddress((void**)&P.aol,  g_ao_l);
    cudaGetSymbolAddress((void**)&P.cath, g_cat_h);
    cudaGetSymbolAddress((void**)&P.catl, g_cat_l);
    cudaGetSymbolAddress((void**)&P.hh,   g_h_h);
    cudaGetSymbolAddress((void**)&P.hl,   g_h_l);
    cudaGetSymbolAddress((void**)&NL1,    g_NL1);
    cudaGetSymbolAddress((void**)&P.inv,  g_inv);
    cudaGetSymbolAddress((void**)&P.cq,   g_cq);
    cudaGetSymbolAddress((void**)&P.wq,   g_wq);
    cudaGetSymbolAddress((void**)&P.wo,   g_wo);
    cudaGetSymbolAddress((void**)&P.w1,   g_w1);
    cudaGetSymbolAddress((void**)&P.w2,   g_w2);
    cudaGetSymbolAddress((void**)&P.wv,   g_wv);
    cudaGetSymbolAddress((void**)&P.wqk,  g_wqk);

    prep_weights<<<3072, 256>>>(Wq, Wo, W1, W2, Wk, Wv,
                                P.wq, P.wo, P.w1, P.w2, P.wv, P.wqk);
    const_q_kernel<<<2, 256>>>(Wq, bq, time_b, P.cq);

    // stage 1: layer-1 embedding of flattened first-hop neighbors (p0)
    gather_emb_kernel<<<M_HOP2, 128>>>(node_feat, memory, neighbors1, P.cath, P.catl, M_HOP2);
    run_layer(P, 0, M_HOP2, neighbors2, nullptr, edge_idx2, edge_times2,
              timestamps, N_K, node_feat, memory, edge_feat, time_w, time_b,
              bk, bv, bo, b1, b2, NL1, nullptr, nullptr, 0);

    // stage 2: layer-1 embedding of src nodes (p0); SL1 -> cat col 256
    gather_emb_kernel<<<N_B, 128>>>(node_feat, memory, src_nodes, P.cath, P.catl, N_B);
    run_layer(P, 0, N_B, neighbors1, nullptr, edge_idx1, edge_times1,
              timestamps, 1, node_feat, memory, edge_feat, time_w, time_b,
              bk, bv, bo, b1, b2, nullptr, P.cath + 256, P.catl + 256, 384);

    // stage 3: layer-2 aggregation (p1), neighbor feats = NL1
    run_layer(P, 1, N_B, neighbors1, NL1, edge_idx1, edge_times1,
              timestamps, 1, node_feat, memory, edge_feat, time_w, time_b,
              bk, bv, bo, b1, b2, (float*)d_out, nullptr, nullptr, 0);
}